// round 8
// baseline (speedup 1.0000x reference)
#include <cuda_runtime.h>
#include <cstdint>

#define HH 64
#define WW 64
#define NPIX 4096
#define NB 4
#define C1 32
#define C2 64
#define C3 256

typedef unsigned long long ull;

__device__ __forceinline__ ull dup2(float v) {
    ull r;
    asm("mov.b64 %0, {%1, %1};" : "=l"(r) : "r"(__float_as_uint(v)));
    return r;
}
__device__ __forceinline__ void ffma2(ull& acc, ull a, ull b) {
    asm("fma.rn.f32x2 %0, %1, %2, %0;" : "+l"(acc) : "l"(a), "l"(b));
}
__device__ __forceinline__ float lo32(ull x) { return __uint_as_float((unsigned int)x); }
__device__ __forceinline__ float hi32(ull x) { return __uint_as_float((unsigned int)(x >> 32)); }
__device__ __forceinline__ uint32_t smem_u32(const void* p) {
    uint32_t a;
    asm("{ .reg .u64 t; cvta.to.shared.u64 t, %1; cvt.u32.u64 %0, t; }" : "=r"(a) : "l"(p));
    return a;
}
#define CP_ASYNC16(dst, src) \
    asm volatile("cp.async.cg.shared.global [%0], [%1], 16;" :: "r"(dst), "l"(src) : "memory")
#define CP_COMMIT() asm volatile("cp.async.commit_group;" ::: "memory")
#define CP_WAIT1() asm volatile("cp.async.wait_group 1;" ::: "memory")
#define CP_WAIT0() asm volatile("cp.async.wait_group 0;" ::: "memory")

// ---------------- static device scratch ----------------
__device__ float g_T1[2 * NB * C1 * NPIX];
__device__ float g_T2[2 * NB * C2 * NPIX];
__device__ float g_F2[NB * C3 * NPIX];
__device__ float g_B2N[NB * NPIX];
__device__ int g_IDX[NB * NPIX];
__device__ float g_Wt2[288 * C2];
__device__ float g_Wt3[576 * C3];
__device__ float g_PVAL[4 * NB * NPIX];
__device__ int g_PIDX[4 * NB * NPIX];
__device__ __align__(16) ull g_QD[(long)NB * C3 * NPIX];  // duplicated queries

// ---------------- prep: weight transposes ----------------
__global__ void prep_kernel(const float* __restrict__ w2, const float* __restrict__ w3,
                            float* __restrict__ Wt2, float* __restrict__ Wt3) {
    int t = blockIdx.x * blockDim.x + threadIdx.x;
    if (t < C2 * 288) {
        int co = t / 288, k = t - co * 288;
        Wt2[k * C2 + co] = w2[t];
    } else {
        int u = t - C2 * 288;
        if (u < C3 * 576) {
            int co = u / 576, k = u - co * 576;
            Wt3[k * C3 + co] = w3[u];
        }
    }
}

// ---------------- conv1 ----------------
__global__ void conv1_kernel(const float* __restrict__ x1, const float* __restrict__ x2,
                             const float* __restrict__ w, const float* __restrict__ bias,
                             float* __restrict__ out) {
    int p = blockIdx.x * blockDim.x + threadIdx.x;
    int z = blockIdx.y;
    if (p >= NPIX) return;
    const float* x = (z >> 2) ? x2 : x1;
    int b = z & 3;
    int y = p >> 6, xx = p & 63;
    const float* xb = x + (long)b * NPIX;
    float in[9];
#pragma unroll
    for (int ky = 0; ky < 3; ky++)
#pragma unroll
        for (int kx = 0; kx < 3; kx++) {
            int yy = y + ky - 1, xc = xx + kx - 1;
            in[ky * 3 + kx] =
                ((unsigned)yy < (unsigned)HH && (unsigned)xc < (unsigned)WW) ? xb[yy * WW + xc] : 0.f;
        }
#pragma unroll 4
    for (int co = 0; co < C1; co++) {
        float acc = bias[co];
#pragma unroll
        for (int t = 0; t < 9; t++) acc += w[co * 9 + t] * in[t];
        out[((long)z * C1 + co) * NPIX + p] = acc;
    }
}

// ---------------- implicit-GEMM conv: BM=64, MP=2, 3 CTAs/SM ----------------
__global__ void __launch_bounds__(256, 3)
conv_gemm_kernel(const float* __restrict__ in, int CI, const float* __restrict__ wT,
                 int Ktot, int CO, const float* __restrict__ bias,
                 float* __restrict__ outA, long strideA, float* __restrict__ outB, long strideB) {
    const int BM = 64, MP = 2;
    __shared__ __align__(16) float As[2][16][BM];   // plain weights (8KB)
    __shared__ __align__(16) ull Bsd[2][16][128];   // duplicated pixels (32KB)
    int z = blockIdx.z;
    int sel = z >> 2, bb = z & 3;
    float* out = sel ? outB : outA;
    long os = sel ? strideB : strideA;
    int m0 = blockIdx.y * BM;
    int n0 = blockIdx.x * 128;
    int tid = threadIdx.x;
    int tx = tid & 15, ty = tid >> 4;
    long inBase = (long)z * CI * NPIX;

    ull acc[MP][8];
#pragma unroll
    for (int u = 0; u < MP; u++)
#pragma unroll
        for (int v = 0; v < 8; v++) acc[u][v] = 0ull;

    float4 av;
    float2 bvp[4];
    int nch = Ktot / 16;

    auto ldA = [&](int c) {
        int k0 = c * 16;
        int k = tid / (BM / 4), p = tid % (BM / 4);
        av = *(const float4*)&wT[(long)(k0 + k) * CO + m0 + p * 4];
    };
    auto ldB = [&](int c) {
        int k0 = c * 16;
#pragma unroll
        for (int i = 0; i < 4; i++) {
            int e2 = tid + i * 256;
            int k = e2 >> 6, np = e2 & 63;
            int gk = k0 + k;
            int ci = gk / 9, tap = gk - ci * 9;
            int kyy = tap / 3 - 1, kxx = tap - (tap / 3) * 3 - 1;
            long cb = inBase + (long)ci * NPIX;
            int gp0 = n0 + np * 2;
            int y0 = (gp0 >> 6) + kyy, x0 = (gp0 & 63) + kxx;
            float v0 = ((unsigned)y0 < (unsigned)HH && (unsigned)x0 < (unsigned)WW)
                           ? in[cb + (y0 << 6) + x0] : 0.f;
            int gp1 = gp0 + 1;
            int y1 = (gp1 >> 6) + kyy, x1 = (gp1 & 63) + kxx;
            float v1 = ((unsigned)y1 < (unsigned)HH && (unsigned)x1 < (unsigned)WW)
                           ? in[cb + (y1 << 6) + x1] : 0.f;
            bvp[i] = make_float2(v0, v1);
        }
    };
    auto stc = [&](int buf) {
        {
            int k = tid / (BM / 4), p = tid % (BM / 4);
            *(float4*)&As[buf][k][p * 4] = av;
        }
#pragma unroll
        for (int i = 0; i < 4; i++) {
            int e2 = tid + i * 256;
            int k = e2 >> 6, np = e2 & 63;
            ulonglong2 t;
            t.x = dup2(bvp[i].x);
            t.y = dup2(bvp[i].y);
            *(ulonglong2*)&Bsd[buf][k][np * 2] = t;
        }
    };

    ldA(0); ldB(0);
    stc(0);
    if (nch > 1) { ldA(1); ldB(1); }
    __syncthreads();

    for (int c = 0; c < nch; c++) {
        int cur = c & 1;
        if (c + 1 < nch) {
            stc(1 - cur);
            if (c + 2 < nch) { ldA(c + 2); ldB(c + 2); }
        }
#pragma unroll
        for (int kk = 0; kk < 16; kk++) {
            ull Ap[MP];
            {
                ulonglong2 t = *(const ulonglong2*)&As[cur][kk][ty * 4];
                Ap[0] = t.x;
                Ap[1] = t.y;
            }
#pragma unroll
            for (int s = 0; s < 4; s++) {
                ulonglong2 bq = *(const ulonglong2*)&Bsd[cur][kk][s * 32 + tx * 2];
#pragma unroll
                for (int mp = 0; mp < MP; mp++) {
                    ffma2(acc[mp][s * 2], Ap[mp], bq.x);
                    ffma2(acc[mp][s * 2 + 1], Ap[mp], bq.y);
                }
            }
        }
        __syncthreads();
    }
#pragma unroll
    for (int mp = 0; mp < MP; mp++) {
        int m = m0 + ty * 4 + mp * 2;
        float b0 = bias[m], b1 = bias[m + 1];
        long base0 = (long)bb * os + (long)m * NPIX + n0;
        long base1 = base0 + NPIX;
#pragma unroll
        for (int s = 0; s < 4; s++) {
            float2 e0, e1;
            e0.x = lo32(acc[mp][s * 2]) + b0;
            e0.y = lo32(acc[mp][s * 2 + 1]) + b0;
            e1.x = hi32(acc[mp][s * 2]) + b1;
            e1.y = hi32(acc[mp][s * 2 + 1]) + b1;
            *(float2*)&out[base0 + s * 32 + tx * 2] = e0;
            *(float2*)&out[base1 + s * 32 + tx * 2] = e1;
        }
    }
}

// ---------------- fused: Q duplication + key row norms ----------------
__global__ void dupq_norm_kernel(const float* __restrict__ f1out, const float* __restrict__ f2,
                                 ull* __restrict__ QD, float* __restrict__ b2n) {
    int bx = blockIdx.x;
    int tid = threadIdx.x;
    if (bx < 8192) {
        long t2 = ((long)bx * 256 + tid) * 2;
        int b = (int)(t2 >> 20);
        int c = (int)((t2 >> 12) & 255);
        int i = (int)(t2 & 4095);
        float2 v = *(const float2*)&f1out[((long)b * 512 + c) * NPIX + i];
        ull* d = &QD[((long)b * C3 + c) * NPIX + i];
        d[0] = dup2(v.x);
        d[1] = dup2(v.y);
    } else {
        int t = (bx - 8192) * 256 + tid;
        int b = t >> 12, j = t & 4095;
        const float* p = f2 + (long)b * C3 * NPIX + j;
        float s = 0.f;
#pragma unroll 8
        for (int c = 0; c < C3; c++) {
            float v = p[(long)c * NPIX];
            s += v * v;
        }
        b2n[t] = s;
    }
}

// ---------------- dist GEMM + argmin: 64i x 128j tile, 3 CTAs/SM, cp.async 3-stage ----------------
#define DSM_ST 16384
#define DSM_TOTAL 49152

__global__ void __launch_bounds__(256, 3)
dist_argmin_kernel(const ull* __restrict__ QD, const float* __restrict__ f2,
                   const float* __restrict__ b2n, float* __restrict__ pval,
                   int* __restrict__ pidx) {
    extern __shared__ __align__(16) char dsm[];
    uint32_t sbase = smem_u32(dsm);
    int b = blockIdx.z;
    int jq = blockIdx.y;
    int i0 = blockIdx.x * 64;
    const ull* Qd = QD + (long)b * C3 * NPIX;
    const float* Kf = f2 + (long)b * C3 * NPIX;
    const float* bn = b2n + (long)b * NPIX;
    int tid = threadIdx.x;
    int tx = tid & 15, ty = tid >> 4;

    float bestv[4];
    int besti[4];
#pragma unroll
    for (int u = 0; u < 4; u++) { bestv[u] = 3.4e38f; besti[u] = 0; }

    ull acc[4][4];
#pragma unroll
    for (int u = 0; u < 4; u++)
#pragma unroll
        for (int v = 0; v < 4; v++) acc[u][v] = 0ull;

    // stage: A = 16 k-rows x 64 dup'd ull (8KB), B = 16 x 128 f32 (8KB)
    auto issue = [&](int c, int st) {
        int k0 = (c & 15) * 16;
        int j0 = jq * 1024 + (c >> 4) * 128;
        uint32_t da = sbase + (uint32_t)st * DSM_ST;
        uint32_t db = da + 8192;
#pragma unroll
        for (int it = 0; it < 2; it++) {
            int e = tid + it * 256;          // 512 x 16B for A
            int row = e >> 5, c16 = e & 31;
            const ull* src = Qd + (long)(k0 + row) * NPIX + i0 + c16 * 2;
            CP_ASYNC16(da + (uint32_t)(row * 512 + c16 * 16), src);
        }
#pragma unroll
        for (int it = 0; it < 2; it++) {
            int e = tid + it * 256;          // 512 x 16B for B
            int row = e >> 5, c16 = e & 31;
            const float* src = Kf + (long)(k0 + row) * NPIX + j0 + c16 * 4;
            CP_ASYNC16(db + (uint32_t)(row * 512 + c16 * 16), src);
        }
        CP_COMMIT();
    };

    const int NCH = 128;  // 8 j-tiles x 16 k-chunks
    issue(0, 0);
    issue(1, 1);

    for (int c = 0; c < NCH; c++) {
        int st = c % 3;
        if (c + 1 < NCH) CP_WAIT1(); else CP_WAIT0();
        __syncthreads();
        if (c + 2 < NCH) issue(c + 2, (c + 2) % 3);
        const ull* AD = (const ull*)(dsm + st * DSM_ST);
        const float* Bs = (const float*)(dsm + st * DSM_ST + 8192);
#pragma unroll
        for (int kk = 0; kk < 16; kk++) {
            ull a2[4];
            {
                ulonglong2 t0 = *(const ulonglong2*)&AD[kk * 64 + ty * 4];
                ulonglong2 t1 = *(const ulonglong2*)&AD[kk * 64 + ty * 4 + 2];
                a2[0] = t0.x; a2[1] = t0.y; a2[2] = t1.x; a2[3] = t1.y;
            }
            ulonglong2 bp0 = *(const ulonglong2*)&Bs[kk * 128 + tx * 8];
            ulonglong2 bp1 = *(const ulonglong2*)&Bs[kk * 128 + tx * 8 + 4];
#pragma unroll
            for (int u = 0; u < 4; u++) {
                ffma2(acc[u][0], a2[u], bp0.x);
                ffma2(acc[u][1], a2[u], bp0.y);
                ffma2(acc[u][2], a2[u], bp1.x);
                ffma2(acc[u][3], a2[u], bp1.y);
            }
        }
        if ((c & 15) == 15) {
            int j0 = jq * 1024 + (c >> 4) * 128;
            // per-thread j ascending (np, then pair lane); strict < keeps first index
#pragma unroll
            for (int np = 0; np < 4; np++) {
                int jj = j0 + tx * 8 + np * 2;
                float bj0 = __ldg(&bn[jj]);
                float bj1 = __ldg(&bn[jj + 1]);
#pragma unroll
                for (int u = 0; u < 4; u++) {
                    ull A = acc[u][np];
                    float d0 = bj0 - 2.f * lo32(A);
                    if (d0 < bestv[u]) { bestv[u] = d0; besti[u] = jj; }
                    float d1 = bj1 - 2.f * hi32(A);
                    if (d1 < bestv[u]) { bestv[u] = d1; besti[u] = jj + 1; }
                    acc[u][np] = 0ull;
                }
            }
        }
    }
    // cross-tx reduction (alias stage smem; cp.async fully drained)
    __syncthreads();
    float* rv = (float*)dsm;                 // 16 x 64 floats
    int* ri = (int*)(dsm + 4096);
#pragma unroll
    for (int u = 0; u < 4; u++) {
        rv[tx * 64 + ty * 4 + u] = bestv[u];
        ri[tx * 64 + ty * 4 + u] = besti[u];
    }
    __syncthreads();
    if (tid < 64) {
        float bv = rv[tid];
        int bi = ri[tid];
#pragma unroll
        for (int t = 1; t < 16; t++) {
            float v = rv[t * 64 + tid];
            int ii = ri[t * 64 + tid];
            if (v < bv || (v == bv && ii < bi)) { bv = v; bi = ii; }
        }
        long o = ((long)jq * NB + b) * NPIX + i0 + tid;
        pval[o] = bv;
        pidx[o] = bi;
    }
}

// ---------------- merge 4 j-quarter candidates ----------------
__global__ void merge_kernel(const float* __restrict__ pval, const int* __restrict__ pidx,
                             int* __restrict__ idxout) {
    int t = blockIdx.x * blockDim.x + threadIdx.x;
    if (t >= NB * NPIX) return;
    int b = t >> 12, i = t & (NPIX - 1);
    float bv = pval[(long)b * NPIX + i];
    int bi = pidx[(long)b * NPIX + i];
#pragma unroll
    for (int jq = 1; jq < 4; jq++) {
        long o = ((long)jq * NB + b) * NPIX + i;
        float v = pval[o];
        int ii = pidx[o];
        if (v < bv || (v == bv && ii < bi)) { bv = v; bi = ii; }
    }
    idxout[t] = bi;
}

// ---------------- gather ----------------
__global__ void gather_kernel(const float* __restrict__ f2, const int* __restrict__ idx,
                              float* __restrict__ out) {
    long t = (long)blockIdx.x * blockDim.x + threadIdx.x;
    if (t >= (long)NB * C3 * NPIX) return;
    int j = (int)(t & (NPIX - 1));
    int c = (int)((t >> 12) & 255);
    int b = (int)(t >> 20);
    int id = idx[(long)b * NPIX + j];
    out[((long)b * 512 + 256 + c) * NPIX + j] = f2[((long)b * C3 + c) * NPIX + id];
}

// ---------------- launch ----------------
extern "C" void kernel_launch(void* const* d_in, const int* in_sizes, int n_in,
                              void* d_out, int out_size) {
    const float* x1 = (const float*)d_in[0];
    const float* x2 = (const float*)d_in[1];
    const float* w1 = (const float*)d_in[2];
    const float* b1 = (const float*)d_in[3];
    const float* w2 = (const float*)d_in[4];
    const float* b2 = (const float*)d_in[5];
    const float* w3 = (const float*)d_in[6];
    const float* b3 = (const float*)d_in[7];
    float* out = (float*)d_out;

    float *T1, *T2, *F2, *B2N, *Wt2, *Wt3, *PVAL;
    int *IDX, *PIDX;
    ull* QD;
    cudaGetSymbolAddress((void**)&T1, g_T1);
    cudaGetSymbolAddress((void**)&T2, g_T2);
    cudaGetSymbolAddress((void**)&F2, g_F2);
    cudaGetSymbolAddress((void**)&B2N, g_B2N);
    cudaGetSymbolAddress((void**)&IDX, g_IDX);
    cudaGetSymbolAddress((void**)&Wt2, g_Wt2);
    cudaGetSymbolAddress((void**)&Wt3, g_Wt3);
    cudaGetSymbolAddress((void**)&PVAL, g_PVAL);
    cudaGetSymbolAddress((void**)&PIDX, g_PIDX);
    cudaGetSymbolAddress((void**)&QD, g_QD);

    cudaFuncSetAttribute(dist_argmin_kernel, cudaFuncAttributeMaxDynamicSharedMemorySize,
                         DSM_TOTAL);

    prep_kernel<<<(C2 * 288 + C3 * 576 + 255) / 256, 256>>>(w2, w3, Wt2, Wt3);
    conv1_kernel<<<dim3(NPIX / 256, 8), 256>>>(x1, x2, w1, b1, T1);
    conv_gemm_kernel<<<dim3(32, 1, 8), 256>>>(
        T1, C1, Wt2, 288, C2, b2, T2, (long)C2 * NPIX, T2 + (long)NB * C2 * NPIX,
        (long)C2 * NPIX);
    conv_gemm_kernel<<<dim3(32, 4, 8), 256>>>(
        T2, C2, Wt3, 576, C3, b3, out, (long)512 * NPIX, F2, (long)C3 * NPIX);
    dupq_norm_kernel<<<8192 + 64, 256>>>(out, F2, QD, B2N);
    dist_argmin_kernel<<<dim3(64, 4, NB), 256, DSM_TOTAL>>>(QD, F2, B2N, PVAL, PIDX);
    merge_kernel<<<(NB * NPIX + 255) / 256, 256>>>(PVAL, PIDX, IDX);
    gather_kernel<<<(int)(((long)NB * C3 * NPIX + 255) / 256), 256>>>(F2, IDX, out);
}

// round 9
// speedup vs baseline: 2.2038x; 2.2038x over previous
#include <cuda_runtime.h>
#include <cstdint>

#define HH 64
#define WW 64
#define NPIX 4096
#define NB 4
#define C1 32
#define C2 64
#define C3 256

typedef unsigned long long ull;

__device__ __forceinline__ ull dup2(float v) {
    ull r;
    asm("mov.b64 %0, {%1, %1};" : "=l"(r) : "r"(__float_as_uint(v)));
    return r;
}
__device__ __forceinline__ void ffma2(ull& acc, ull a, ull b) {
    asm("fma.rn.f32x2 %0, %1, %2, %0;" : "+l"(acc) : "l"(a), "l"(b));
}
__device__ __forceinline__ float lo32(ull x) { return __uint_as_float((unsigned int)x); }
__device__ __forceinline__ float hi32(ull x) { return __uint_as_float((unsigned int)(x >> 32)); }
__device__ __forceinline__ uint32_t smem_u32(const void* p) {
    uint32_t a;
    asm("{ .reg .u64 t; cvta.to.shared.u64 t, %1; cvt.u32.u64 %0, t; }" : "=r"(a) : "l"(p));
    return a;
}
#define CP_ASYNC16(dst, src) \
    asm volatile("cp.async.cg.shared.global [%0], [%1], 16;" :: "r"(dst), "l"(src) : "memory")
#define CP_COMMIT() asm volatile("cp.async.commit_group;" ::: "memory")
#define CP_WAIT1() asm volatile("cp.async.wait_group 1;" ::: "memory")
#define CP_WAIT0() asm volatile("cp.async.wait_group 0;" ::: "memory")

// ---------------- static device scratch ----------------
__device__ float g_T1[2 * NB * C1 * NPIX];
__device__ float g_T2[2 * NB * C2 * NPIX];
__device__ float g_F2[NB * C3 * NPIX];
__device__ float g_B2N[NB * NPIX];
__device__ int g_IDX[NB * NPIX];
__device__ float g_Wt2[288 * C2];
__device__ float g_Wt3[576 * C3];
__device__ float g_PVAL[4 * NB * NPIX];
__device__ int g_PIDX[4 * NB * NPIX];
__device__ __align__(16) ull g_QD[(long)NB * C3 * NPIX];

// ---------------- prep: weight transposes ----------------
__global__ void prep_kernel(const float* __restrict__ w2, const float* __restrict__ w3,
                            float* __restrict__ Wt2, float* __restrict__ Wt3) {
    int t = blockIdx.x * blockDim.x + threadIdx.x;
    if (t < C2 * 288) {
        int co = t / 288, k = t - co * 288;
        Wt2[k * C2 + co] = w2[t];
    } else {
        int u = t - C2 * 288;
        if (u < C3 * 576) {
            int co = u / 576, k = u - co * 576;
            Wt3[k * C3 + co] = w3[u];
        }
    }
}

// ---------------- conv1 ----------------
__global__ void conv1_kernel(const float* __restrict__ x1, const float* __restrict__ x2,
                             const float* __restrict__ w, const float* __restrict__ bias,
                             float* __restrict__ out) {
    int p = blockIdx.x * blockDim.x + threadIdx.x;
    int z = blockIdx.y;
    if (p >= NPIX) return;
    const float* x = (z >> 2) ? x2 : x1;
    int b = z & 3;
    int y = p >> 6, xx = p & 63;
    const float* xb = x + (long)b * NPIX;
    float in[9];
#pragma unroll
    for (int ky = 0; ky < 3; ky++)
#pragma unroll
        for (int kx = 0; kx < 3; kx++) {
            int yy = y + ky - 1, xc = xx + kx - 1;
            in[ky * 3 + kx] =
                ((unsigned)yy < (unsigned)HH && (unsigned)xc < (unsigned)WW) ? xb[yy * WW + xc] : 0.f;
        }
#pragma unroll 4
    for (int co = 0; co < C1; co++) {
        float acc = bias[co];
#pragma unroll
        for (int t = 0; t < 9; t++) acc += w[co * 9 + t] * in[t];
        out[((long)z * C1 + co) * NPIX + p] = acc;
    }
}

// ---------------- implicit-GEMM conv (round-6 proven version) ----------------
template <int BM, int MP>
__global__ void __launch_bounds__(256, 2)
conv_gemm_kernel(const float* __restrict__ in, int CI, const float* __restrict__ wT,
                 int Ktot, int CO, const float* __restrict__ bias,
                 float* __restrict__ outA, long strideA, float* __restrict__ outB, long strideB) {
    __shared__ __align__(16) float As[2][16][BM];
    __shared__ __align__(16) ull Bsd[2][16][128];
    int z = blockIdx.z;
    int sel = z >> 2, bb = z & 3;
    float* out = sel ? outB : outA;
    long os = sel ? strideB : strideA;
    int m0 = blockIdx.y * BM;
    int n0 = blockIdx.x * 128;
    int tid = threadIdx.x;
    int tx = tid & 15, ty = tid >> 4;
    long inBase = (long)z * CI * NPIX;
    const int NA4 = BM / 64;

    ull acc[MP][8];
#pragma unroll
    for (int u = 0; u < MP; u++)
#pragma unroll
        for (int v = 0; v < 8; v++) acc[u][v] = 0ull;

    float4 av[NA4];
    float2 bvp[4];
    int nch = Ktot / 16;

    auto ldA = [&](int c) {
        int k0 = c * 16;
#pragma unroll
        for (int i = 0; i < NA4; i++) {
            int e = tid + i * 256;
            int k = e / (BM / 4), p = e % (BM / 4);
            av[i] = *(const float4*)&wT[(long)(k0 + k) * CO + m0 + p * 4];
        }
    };
    auto ldB = [&](int c) {
        int k0 = c * 16;
#pragma unroll
        for (int i = 0; i < 4; i++) {
            int e2 = tid + i * 256;
            int k = e2 >> 6, np = e2 & 63;
            int gk = k0 + k;
            int ci = gk / 9, tap = gk - ci * 9;
            int kyy = tap / 3 - 1, kxx = tap - (tap / 3) * 3 - 1;
            long cb = inBase + (long)ci * NPIX;
            int gp0 = n0 + np * 2;
            int y0 = (gp0 >> 6) + kyy, x0 = (gp0 & 63) + kxx;
            float v0 = ((unsigned)y0 < (unsigned)HH && (unsigned)x0 < (unsigned)WW)
                           ? in[cb + (y0 << 6) + x0] : 0.f;
            int gp1 = gp0 + 1;
            int y1 = (gp1 >> 6) + kyy, x1 = (gp1 & 63) + kxx;
            float v1 = ((unsigned)y1 < (unsigned)HH && (unsigned)x1 < (unsigned)WW)
                           ? in[cb + (y1 << 6) + x1] : 0.f;
            bvp[i] = make_float2(v0, v1);
        }
    };
    auto stc = [&](int buf) {
#pragma unroll
        for (int i = 0; i < NA4; i++) {
            int e = tid + i * 256;
            int k = e / (BM / 4), p = e % (BM / 4);
            *(float4*)&As[buf][k][p * 4] = av[i];
        }
#pragma unroll
        for (int i = 0; i < 4; i++) {
            int e2 = tid + i * 256;
            int k = e2 >> 6, np = e2 & 63;
            ulonglong2 t;
            t.x = dup2(bvp[i].x);
            t.y = dup2(bvp[i].y);
            *(ulonglong2*)&Bsd[buf][k][np * 2] = t;
        }
    };

    ldA(0); ldB(0);
    stc(0);
    if (nch > 1) { ldA(1); ldB(1); }
    __syncthreads();

    for (int c = 0; c < nch; c++) {
        int cur = c & 1;
        if (c + 1 < nch) {
            stc(1 - cur);
            if (c + 2 < nch) { ldA(c + 2); ldB(c + 2); }
        }
#pragma unroll
        for (int kk = 0; kk < 16; kk++) {
            ull Ap[MP];
#pragma unroll
            for (int h = 0; h < MP / 2; h++) {
                ulonglong2 t = *(const ulonglong2*)&As[cur][kk][ty * 2 * MP + h * 4];
                Ap[h * 2] = t.x;
                Ap[h * 2 + 1] = t.y;
            }
#pragma unroll
            for (int s = 0; s < 4; s++) {
                ulonglong2 bq = *(const ulonglong2*)&Bsd[cur][kk][s * 32 + tx * 2];
#pragma unroll
                for (int mp = 0; mp < MP; mp++) {
                    ffma2(acc[mp][s * 2], Ap[mp], bq.x);
                    ffma2(acc[mp][s * 2 + 1], Ap[mp], bq.y);
                }
            }
        }
        __syncthreads();
    }
#pragma unroll
    for (int mp = 0; mp < MP; mp++) {
        int m = m0 + ty * 2 * MP + mp * 2;
        float b0 = bias[m], b1 = bias[m + 1];
        long base0 = (long)bb * os + (long)m * NPIX + n0;
        long base1 = base0 + NPIX;
#pragma unroll
        for (int s = 0; s < 4; s++) {
            float2 e0, e1;
            e0.x = lo32(acc[mp][s * 2]) + b0;
            e0.y = lo32(acc[mp][s * 2 + 1]) + b0;
            e1.x = hi32(acc[mp][s * 2]) + b1;
            e1.y = hi32(acc[mp][s * 2 + 1]) + b1;
            *(float2*)&out[base0 + s * 32 + tx * 2] = e0;
            *(float2*)&out[base1 + s * 32 + tx * 2] = e1;
        }
    }
}

// ---------------- fused: Q duplication + key row norms ----------------
__global__ void dupq_norm_kernel(const float* __restrict__ f1out, const float* __restrict__ f2,
                                 ull* __restrict__ QD, float* __restrict__ b2n) {
    int bx = blockIdx.x;
    int tid = threadIdx.x;
    if (bx < 8192) {
        long t2 = ((long)bx * 256 + tid) * 2;
        int b = (int)(t2 >> 20);
        int c = (int)((t2 >> 12) & 255);
        int i = (int)(t2 & 4095);
        float2 v = *(const float2*)&f1out[((long)b * 512 + c) * NPIX + i];
        ull* d = &QD[((long)b * C3 + c) * NPIX + i];
        d[0] = dup2(v.x);
        d[1] = dup2(v.y);
    } else {
        int t = (bx - 8192) * 256 + tid;
        int b = t >> 12, j = t & 4095;
        const float* p = f2 + (long)b * C3 * NPIX + j;
        float s = 0.f;
#pragma unroll 8
        for (int c = 0; c < C3; c++) {
            float v = p[(long)c * NPIX];
            s += v * v;
        }
        b2n[t] = s;
    }
}

// ---------------- dist GEMM + argmin: 128i x 128j, cp.async 3-stage, pipelined kk ----------------
#define DSM_A(st) ((st) * 16384)
#define DSM_B(st) (49152 + (st) * 8192)
#define DSM_TOTAL 73728

__global__ void __launch_bounds__(256, 2)
dist_argmin_kernel(const ull* __restrict__ QD, const float* __restrict__ f2,
                   const float* __restrict__ b2n, float* __restrict__ pval,
                   int* __restrict__ pidx) {
    extern __shared__ __align__(16) char dsm[];
    uint32_t sbase = smem_u32(dsm);
    int b = blockIdx.z;
    int jq = blockIdx.y;
    int i0 = blockIdx.x * 128;
    const ull* Qd = QD + (long)b * C3 * NPIX;
    const float* Kf = f2 + (long)b * C3 * NPIX;
    const float* bn = b2n + (long)b * NPIX;
    int tid = threadIdx.x;
    int tx = tid & 15, ty = tid >> 4;

    float bestv[8];
    int besti[8];
#pragma unroll
    for (int u = 0; u < 8; u++) { bestv[u] = 3.4e38f; besti[u] = 0; }

    ull acc[8][4];
#pragma unroll
    for (int u = 0; u < 8; u++)
#pragma unroll
        for (int v = 0; v < 4; v++) acc[u][v] = 0ull;

    auto issue = [&](int c, int st) {
        int k0 = (c & 15) * 16;
        int j0 = jq * 1024 + (c >> 4) * 128;
        uint32_t da = sbase + DSM_A(st);
        uint32_t db = sbase + DSM_B(st);
#pragma unroll
        for (int it = 0; it < 4; it++) {
            int e = tid + it * 256;
            int row = e >> 6, c16 = e & 63;
            const ull* src = Qd + (long)(k0 + row) * NPIX + i0 + c16 * 2;
            CP_ASYNC16(da + (uint32_t)(row * 1024 + c16 * 16), src);
        }
#pragma unroll
        for (int it = 0; it < 2; it++) {
            int e = tid + it * 256;
            int row = e >> 5, c16 = e & 31;
            const float* src = Kf + (long)(k0 + row) * NPIX + j0 + c16 * 4;
            CP_ASYNC16(db + (uint32_t)(row * 512 + c16 * 16), src);
        }
        CP_COMMIT();
    };

    const int NCH = 128;
    issue(0, 0);
    issue(1, 1);

    for (int c = 0; c < NCH; c++) {
        int st = c % 3;
        if (c + 1 < NCH) CP_WAIT1(); else CP_WAIT0();
        __syncthreads();
        if (c + 2 < NCH) issue(c + 2, (c + 2) % 3);
        const ull* AD = (const ull*)(dsm + DSM_A(st));
        const float* Bs = (const float*)(dsm + DSM_B(st));

        // explicit operand pipelining: load A for kk+1 while FMAing kk
        ull a2[2][8];
#pragma unroll
        for (int h = 0; h < 4; h++) {
            ulonglong2 t = *(const ulonglong2*)&AD[ty * 8 + h * 2];
            a2[0][h * 2] = t.x;
            a2[0][h * 2 + 1] = t.y;
        }
#pragma unroll
        for (int kk = 0; kk < 16; kk++) {
            int cur = kk & 1;
            if (kk < 15) {
#pragma unroll
                for (int h = 0; h < 4; h++) {
                    ulonglong2 t = *(const ulonglong2*)&AD[(kk + 1) * 128 + ty * 8 + h * 2];
                    a2[1 - cur][h * 2] = t.x;
                    a2[1 - cur][h * 2 + 1] = t.y;
                }
            }
            ulonglong2 bp0 = *(const ulonglong2*)&Bs[kk * 128 + tx * 8];
            ulonglong2 bp1 = *(const ulonglong2*)&Bs[kk * 128 + tx * 8 + 4];
#pragma unroll
            for (int u = 0; u < 8; u++) {
                ffma2(acc[u][0], a2[cur][u], bp0.x);
                ffma2(acc[u][1], a2[cur][u], bp0.y);
                ffma2(acc[u][2], a2[cur][u], bp1.x);
                ffma2(acc[u][3], a2[cur][u], bp1.y);
            }
        }
        if ((c & 15) == 15) {
            int j0 = jq * 1024 + (c >> 4) * 128;
            // per-thread j ascending (np, then pair lane); strict < keeps first index
#pragma unroll
            for (int np = 0; np < 4; np++) {
                int jj = j0 + tx * 8 + np * 2;
                float bj0 = __ldg(&bn[jj]);
                float bj1 = __ldg(&bn[jj + 1]);
#pragma unroll
                for (int u = 0; u < 8; u++) {
                    ull A = acc[u][np];
                    float d0 = bj0 - 2.f * lo32(A);
                    if (d0 < bestv[u]) { bestv[u] = d0; besti[u] = jj; }
                    float d1 = bj1 - 2.f * hi32(A);
                    if (d1 < bestv[u]) { bestv[u] = d1; besti[u] = jj + 1; }
                    acc[u][np] = 0ull;
                }
            }
        }
    }
    // cross-tx reduction (alias stage smem; cp.async fully drained by WAIT0)
    __syncthreads();
    float* rv = (float*)dsm;
    int* ri = (int*)(dsm + 8192);
#pragma unroll
    for (int u = 0; u < 8; u++) {
        rv[tx * 128 + ty * 8 + u] = bestv[u];
        ri[tx * 128 + ty * 8 + u] = besti[u];
    }
    __syncthreads();
    if (tid < 128) {
        float bv = rv[tid];
        int bi = ri[tid];
#pragma unroll
        for (int t = 1; t < 16; t++) {
            float v = rv[t * 128 + tid];
            int ii = ri[t * 128 + tid];
            if (v < bv || (v == bv && ii < bi)) { bv = v; bi = ii; }
        }
        long o = ((long)jq * NB + b) * NPIX + i0 + tid;
        pval[o] = bv;
        pidx[o] = bi;
    }
}

// ---------------- merge 4 j-quarter candidates ----------------
__global__ void merge_kernel(const float* __restrict__ pval, const int* __restrict__ pidx,
                             int* __restrict__ idxout) {
    int t = blockIdx.x * blockDim.x + threadIdx.x;
    if (t >= NB * NPIX) return;
    int b = t >> 12, i = t & (NPIX - 1);
    float bv = pval[(long)b * NPIX + i];
    int bi = pidx[(long)b * NPIX + i];
#pragma unroll
    for (int jq = 1; jq < 4; jq++) {
        long o = ((long)jq * NB + b) * NPIX + i;
        float v = pval[o];
        int ii = pidx[o];
        if (v < bv || (v == bv && ii < bi)) { bv = v; bi = ii; }
    }
    idxout[t] = bi;
}

// ---------------- gather ----------------
__global__ void gather_kernel(const float* __restrict__ f2, const int* __restrict__ idx,
                              float* __restrict__ out) {
    long t = (long)blockIdx.x * blockDim.x + threadIdx.x;
    if (t >= (long)NB * C3 * NPIX) return;
    int j = (int)(t & (NPIX - 1));
    int c = (int)((t >> 12) & 255);
    int b = (int)(t >> 20);
    int id = idx[(long)b * NPIX + j];
    out[((long)b * 512 + 256 + c) * NPIX + j] = f2[((long)b * C3 + c) * NPIX + id];
}

// ---------------- launch ----------------
extern "C" void kernel_launch(void* const* d_in, const int* in_sizes, int n_in,
                              void* d_out, int out_size) {
    const float* x1 = (const float*)d_in[0];
    const float* x2 = (const float*)d_in[1];
    const float* w1 = (const float*)d_in[2];
    const float* b1 = (const float*)d_in[3];
    const float* w2 = (const float*)d_in[4];
    const float* b2 = (const float*)d_in[5];
    const float* w3 = (const float*)d_in[6];
    const float* b3 = (const float*)d_in[7];
    float* out = (float*)d_out;

    float *T1, *T2, *F2, *B2N, *Wt2, *Wt3, *PVAL;
    int *IDX, *PIDX;
    ull* QD;
    cudaGetSymbolAddress((void**)&T1, g_T1);
    cudaGetSymbolAddress((void**)&T2, g_T2);
    cudaGetSymbolAddress((void**)&F2, g_F2);
    cudaGetSymbolAddress((void**)&B2N, g_B2N);
    cudaGetSymbolAddress((void**)&IDX, g_IDX);
    cudaGetSymbolAddress((void**)&Wt2, g_Wt2);
    cudaGetSymbolAddress((void**)&Wt3, g_Wt3);
    cudaGetSymbolAddress((void**)&PVAL, g_PVAL);
    cudaGetSymbolAddress((void**)&PIDX, g_PIDX);
    cudaGetSymbolAddress((void**)&QD, g_QD);

    cudaFuncSetAttribute(dist_argmin_kernel, cudaFuncAttributeMaxDynamicSharedMemorySize,
                         DSM_TOTAL);

    prep_kernel<<<(C2 * 288 + C3 * 576 + 255) / 256, 256>>>(w2, w3, Wt2, Wt3);
    conv1_kernel<<<dim3(NPIX / 256, 8), 256>>>(x1, x2, w1, b1, T1);
    conv_gemm_kernel<64, 2><<<dim3(32, 1, 8), 256>>>(
        T1, C1, Wt2, 288, C2, b2, T2, (long)C2 * NPIX, T2 + (long)NB * C2 * NPIX,
        (long)C2 * NPIX);
    conv_gemm_kernel<128, 4><<<dim3(32, 2, 8), 256>>>(
        T2, C2, Wt3, 576, C3, b3, out, (long)512 * NPIX, F2, (long)C3 * NPIX);
    dupq_norm_kernel<<<8192 + 64, 256>>>(out, F2, QD, B2N);
    dist_argmin_kernel<<<dim3(32, 4, NB), 256, DSM_TOTAL>>>(QD, F2, B2N, PVAL, PIDX);
    merge_kernel<<<(NB * NPIX + 255) / 256, 256>>>(PVAL, PIDX, IDX);
    gather_kernel<<<(int)(((long)NB * C3 * NPIX + 255) / 256), 256>>>(F2, IDX, out);
}

// round 10
// speedup vs baseline: 2.2577x; 1.0244x over previous
#include <cuda_runtime.h>
#include <cstdint>

#define HH 64
#define WW 64
#define NPIX 4096
#define NB 4
#define C1 32
#define C2 64
#define C3 256

typedef unsigned long long ull;

__device__ __forceinline__ ull dup2(float v) {
    ull r;
    asm("mov.b64 %0, {%1, %1};" : "=l"(r) : "r"(__float_as_uint(v)));
    return r;
}
__device__ __forceinline__ void ffma2(ull& acc, ull a, ull b) {
    asm("fma.rn.f32x2 %0, %1, %2, %0;" : "+l"(acc) : "l"(a), "l"(b));
}
__device__ __forceinline__ float lo32(ull x) { return __uint_as_float((unsigned int)x); }
__device__ __forceinline__ float hi32(ull x) { return __uint_as_float((unsigned int)(x >> 32)); }
__device__ __forceinline__ uint32_t smem_u32(const void* p) {
    uint32_t a;
    asm("{ .reg .u64 t; cvta.to.shared.u64 t, %1; cvt.u32.u64 %0, t; }" : "=r"(a) : "l"(p));
    return a;
}
#define CP_ASYNC16(dst, src) \
    asm volatile("cp.async.cg.shared.global [%0], [%1], 16;" :: "r"(dst), "l"(src) : "memory")
#define CP_COMMIT() asm volatile("cp.async.commit_group;" ::: "memory")
#define CP_WAIT1() asm volatile("cp.async.wait_group 1;" ::: "memory")
#define CP_WAIT0() asm volatile("cp.async.wait_group 0;" ::: "memory")

// ---------------- static device scratch ----------------
__device__ float g_T1[2 * NB * C1 * NPIX];
__device__ float g_T2[2 * NB * C2 * NPIX];
__device__ float g_F2[NB * C3 * NPIX];
__device__ float g_B2N[NB * NPIX];
__device__ int g_IDX[NB * NPIX];
__device__ __align__(16) ull g_Wt2D[288 * C2];   // dup'd weights [k][co]
__device__ __align__(16) ull g_Wt3D[576 * C3];
__device__ float g_PVAL[4 * NB * NPIX];
__device__ int g_PIDX[4 * NB * NPIX];
__device__ __align__(16) ull g_QD[(long)NB * C3 * NPIX];

// ---------------- prep: transpose + duplicate weights ----------------
__global__ void prep_kernel(const float* __restrict__ w2, const float* __restrict__ w3,
                            ull* __restrict__ Wt2D, ull* __restrict__ Wt3D) {
    int t = blockIdx.x * blockDim.x + threadIdx.x;
    if (t < C2 * 288) {
        int co = t / 288, k = t - co * 288;
        Wt2D[k * C2 + co] = dup2(w2[t]);
    } else {
        int u = t - C2 * 288;
        if (u < C3 * 576) {
            int co = u / 576, k = u - co * 576;
            Wt3D[k * C3 + co] = dup2(w3[u]);
        }
    }
}

// ---------------- conv1 ----------------
__global__ void conv1_kernel(const float* __restrict__ x1, const float* __restrict__ x2,
                             const float* __restrict__ w, const float* __restrict__ bias,
                             float* __restrict__ out) {
    int p = blockIdx.x * blockDim.x + threadIdx.x;
    int z = blockIdx.y;
    if (p >= NPIX) return;
    const float* x = (z >> 2) ? x2 : x1;
    int b = z & 3;
    int y = p >> 6, xx = p & 63;
    const float* xb = x + (long)b * NPIX;
    float in[9];
#pragma unroll
    for (int ky = 0; ky < 3; ky++)
#pragma unroll
        for (int kx = 0; kx < 3; kx++) {
            int yy = y + ky - 1, xc = xx + kx - 1;
            in[ky * 3 + kx] =
                ((unsigned)yy < (unsigned)HH && (unsigned)xc < (unsigned)WW) ? xb[yy * WW + xc] : 0.f;
        }
#pragma unroll 4
    for (int co = 0; co < C1; co++) {
        float acc = bias[co];
#pragma unroll
        for (int t = 0; t < 9; t++) acc += w[co * 9 + t] * in[t];
        out[((long)z * C1 + co) * NPIX + p] = acc;
    }
}

// ---------------- implicit-GEMM conv: dup'd A, plain strided B (conflict-free) ----------------
// TM = BM/16. acc[TM][4]: m = ty*TM+u, j-pair at n = s*32 + tx*2.
template <int BM, int TM>
__global__ void __launch_bounds__(256, 2)
conv_gemm_kernel(const float* __restrict__ in, int CI, const ull* __restrict__ WtD,
                 int Ktot, int CO, const float* __restrict__ bias,
                 float* __restrict__ outA, long strideA, float* __restrict__ outB, long strideB) {
    __shared__ __align__(16) ull AD[2][16][BM];     // dup'd weights
    __shared__ __align__(16) float Bs[2][16][128];  // plain pixels
    int z = blockIdx.z;
    int sel = z >> 2, bb = z & 3;
    float* out = sel ? outB : outA;
    long os = sel ? strideB : strideA;
    int m0 = blockIdx.y * BM;
    int n0 = blockIdx.x * 128;
    int tid = threadIdx.x;
    int tx = tid & 15, ty = tid >> 4;
    long inBase = (long)z * CI * NPIX;
    const int NAV = BM / 32;  // ulonglong2 A loads per thread per chunk

    ull acc[TM][4];
#pragma unroll
    for (int u = 0; u < TM; u++)
#pragma unroll
        for (int v = 0; v < 4; v++) acc[u][v] = 0ull;

    ulonglong2 avd[NAV];
    float2 bvp[4];
    int nch = Ktot / 16;
    const ulonglong2* W2 = (const ulonglong2*)WtD;  // row CO/2

    auto ldA = [&](int c) {
        int k0 = c * 16;
#pragma unroll
        for (int i = 0; i < NAV; i++) {
            int e = tid + i * 256;
            int k = e / (BM / 2), c2 = e % (BM / 2);
            avd[i] = W2[(long)(k0 + k) * (CO / 2) + (m0 >> 1) + c2];
        }
    };
    auto ldB = [&](int c) {
        int k0 = c * 16;
#pragma unroll
        for (int i = 0; i < 4; i++) {
            int e2 = tid + i * 256;
            int k = e2 >> 6, np = e2 & 63;
            int gk = k0 + k;
            int ci = gk / 9, tap = gk - ci * 9;
            int kyy = tap / 3 - 1, kxx = tap - (tap / 3) * 3 - 1;
            long cb = inBase + (long)ci * NPIX;
            int gp0 = n0 + np * 2;
            int y0 = (gp0 >> 6) + kyy, x0 = (gp0 & 63) + kxx;
            float v0 = ((unsigned)y0 < (unsigned)HH && (unsigned)x0 < (unsigned)WW)
                           ? in[cb + (y0 << 6) + x0] : 0.f;
            int gp1 = gp0 + 1;
            int y1 = (gp1 >> 6) + kyy, x1 = (gp1 & 63) + kxx;
            float v1 = ((unsigned)y1 < (unsigned)HH && (unsigned)x1 < (unsigned)WW)
                           ? in[cb + (y1 << 6) + x1] : 0.f;
            bvp[i] = make_float2(v0, v1);
        }
    };
    auto stc = [&](int buf) {
        ulonglong2* AD2 = (ulonglong2*)&AD[buf][0][0];
#pragma unroll
        for (int i = 0; i < NAV; i++) {
            int e = tid + i * 256;
            AD2[e] = avd[i];
        }
#pragma unroll
        for (int i = 0; i < 4; i++) {
            int e2 = tid + i * 256;
            int k = e2 >> 6, np = e2 & 63;
            *(float2*)&Bs[buf][k][np * 2] = bvp[i];
        }
    };

    ldA(0); ldB(0);
    stc(0);
    if (nch > 1) { ldA(1); ldB(1); }
    __syncthreads();

    for (int c = 0; c < nch; c++) {
        int cur = c & 1;
        if (c + 1 < nch) {
            stc(1 - cur);
            if (c + 2 < nch) { ldA(c + 2); ldB(c + 2); }
        }
#pragma unroll
        for (int kk = 0; kk < 16; kk++) {
            ull a2[TM];
#pragma unroll
            for (int h = 0; h < TM / 2; h++) {
                ulonglong2 t = *(const ulonglong2*)&AD[cur][kk][ty * TM + h * 2];
                a2[h * 2] = t.x;
                a2[h * 2 + 1] = t.y;
            }
            const ull* brow = (const ull*)&Bs[cur][kk][0];
            ull bq[4];
#pragma unroll
            for (int s = 0; s < 4; s++) bq[s] = brow[s * 16 + tx];
#pragma unroll
            for (int u = 0; u < TM; u++)
#pragma unroll
                for (int s = 0; s < 4; s++) ffma2(acc[u][s], a2[u], bq[s]);
        }
        __syncthreads();
    }
#pragma unroll
    for (int u = 0; u < TM; u++) {
        int m = m0 + ty * TM + u;
        float bval = bias[m];
        long base = (long)bb * os + (long)m * NPIX + n0;
#pragma unroll
        for (int s = 0; s < 4; s++) {
            float2 o;
            o.x = lo32(acc[u][s]) + bval;
            o.y = hi32(acc[u][s]) + bval;
            *(float2*)&out[base + s * 32 + tx * 2] = o;
        }
    }
}

// ---------------- fused: Q duplication + key row norms ----------------
__global__ void dupq_norm_kernel(const float* __restrict__ f1out, const float* __restrict__ f2,
                                 ull* __restrict__ QD, float* __restrict__ b2n) {
    int bx = blockIdx.x;
    int tid = threadIdx.x;
    if (bx < 8192) {
        long t2 = ((long)bx * 256 + tid) * 2;
        int b = (int)(t2 >> 20);
        int c = (int)((t2 >> 12) & 255);
        int i = (int)(t2 & 4095);
        float2 v = *(const float2*)&f1out[((long)b * 512 + c) * NPIX + i];
        ull* d = &QD[((long)b * C3 + c) * NPIX + i];
        d[0] = dup2(v.x);
        d[1] = dup2(v.y);
    } else {
        int t = (bx - 8192) * 256 + tid;
        int b = t >> 12, j = t & 4095;
        const float* p = f2 + (long)b * C3 * NPIX + j;
        float s = 0.f;
#pragma unroll 8
        for (int c = 0; c < C3; c++) {
            float v = p[(long)c * NPIX];
            s += v * v;
        }
        b2n[t] = s;
    }
}

// ---------------- dist GEMM + argmin: conflict-free strided B, cp.async 3-stage ----------------
#define DSM_A(st) ((st) * 16384)
#define DSM_B(st) (49152 + (st) * 8192)
#define DSM_TOTAL 73728

__global__ void __launch_bounds__(256, 2)
dist_argmin_kernel(const ull* __restrict__ QD, const float* __restrict__ f2,
                   const float* __restrict__ b2n, float* __restrict__ pval,
                   int* __restrict__ pidx) {
    extern __shared__ __align__(16) char dsm[];
    uint32_t sbase = smem_u32(dsm);
    int b = blockIdx.z;
    int jq = blockIdx.y;
    int i0 = blockIdx.x * 128;
    const ull* Qd = QD + (long)b * C3 * NPIX;
    const float* Kf = f2 + (long)b * C3 * NPIX;
    const float* bn = b2n + (long)b * NPIX;
    int tid = threadIdx.x;
    int tx = tid & 15, ty = tid >> 4;

    float bestv[8];
    int besti[8];
#pragma unroll
    for (int u = 0; u < 8; u++) { bestv[u] = 3.4e38f; besti[u] = 0; }

    ull acc[8][4];  // i = ty*8+u ; j-pair at s*32 + tx*2
#pragma unroll
    for (int u = 0; u < 8; u++)
#pragma unroll
        for (int v = 0; v < 4; v++) acc[u][v] = 0ull;

    auto issue = [&](int c, int st) {
        int k0 = (c & 15) * 16;
        int j0 = jq * 1024 + (c >> 4) * 128;
        uint32_t da = sbase + DSM_A(st);
        uint32_t db = sbase + DSM_B(st);
#pragma unroll
        for (int it = 0; it < 4; it++) {
            int e = tid + it * 256;
            int row = e >> 6, c16 = e & 63;
            const ull* src = Qd + (long)(k0 + row) * NPIX + i0 + c16 * 2;
            CP_ASYNC16(da + (uint32_t)(row * 1024 + c16 * 16), src);
        }
#pragma unroll
        for (int it = 0; it < 2; it++) {
            int e = tid + it * 256;
            int row = e >> 5, c16 = e & 31;
            const float* src = Kf + (long)(k0 + row) * NPIX + j0 + c16 * 4;
            CP_ASYNC16(db + (uint32_t)(row * 512 + c16 * 16), src);
        }
        CP_COMMIT();
    };

    const int NCH = 128;
    issue(0, 0);
    issue(1, 1);

    for (int c = 0; c < NCH; c++) {
        int st = c % 3;
        if (c + 1 < NCH) CP_WAIT1(); else CP_WAIT0();
        __syncthreads();
        if (c + 2 < NCH) issue(c + 2, (c + 2) % 3);
        const ull* AD = (const ull*)(dsm + DSM_A(st));    // [16][128] dup'd
        const ull* BsU = (const ull*)(dsm + DSM_B(st));   // [16][64] plain pairs
#pragma unroll
        for (int kk = 0; kk < 16; kk++) {
            ull a2[8];
#pragma unroll
            for (int h = 0; h < 4; h++) {
                ulonglong2 t = *(const ulonglong2*)&AD[kk * 128 + ty * 8 + h * 2];
                a2[h * 2] = t.x;
                a2[h * 2 + 1] = t.y;
            }
            ull bq[4];
#pragma unroll
            for (int s = 0; s < 4; s++) bq[s] = BsU[kk * 64 + s * 16 + tx];
#pragma unroll
            for (int u = 0; u < 8; u++)
#pragma unroll
                for (int s = 0; s < 4; s++) ffma2(acc[u][s], a2[u], bq[s]);
        }
        if ((c & 15) == 15) {
            int j0 = jq * 1024 + (c >> 4) * 128;
            // per-thread j ascending in s; strict < keeps first index
#pragma unroll
            for (int s = 0; s < 4; s++) {
                int jj = j0 + s * 32 + tx * 2;
                float bj0 = __ldg(&bn[jj]);
                float bj1 = __ldg(&bn[jj + 1]);
#pragma unroll
                for (int u = 0; u < 8; u++) {
                    ull A = acc[u][s];
                    float d0 = bj0 - 2.f * lo32(A);
                    if (d0 < bestv[u]) { bestv[u] = d0; besti[u] = jj; }
                    float d1 = bj1 - 2.f * hi32(A);
                    if (d1 < bestv[u]) { bestv[u] = d1; besti[u] = jj + 1; }
                    acc[u][s] = 0ull;
                }
            }
        }
    }
    // cross-tx reduction (alias stage smem; cp.async fully drained by WAIT0)
    __syncthreads();
    float* rv = (float*)dsm;
    int* ri = (int*)(dsm + 8192);
#pragma unroll
    for (int u = 0; u < 8; u++) {
        rv[tx * 128 + ty * 8 + u] = bestv[u];
        ri[tx * 128 + ty * 8 + u] = besti[u];
    }
    __syncthreads();
    if (tid < 128) {
        float bv = rv[tid];
        int bi = ri[tid];
#pragma unroll
        for (int t = 1; t < 16; t++) {
            float v = rv[t * 128 + tid];
            int ii = ri[t * 128 + tid];
            if (v < bv || (v == bv && ii < bi)) { bv = v; bi = ii; }
        }
        long o = ((long)jq * NB + b) * NPIX + i0 + tid;
        pval[o] = bv;
        pidx[o] = bi;
    }
}

// ---------------- merge 4 j-quarter candidates ----------------
__global__ void merge_kernel(const float* __restrict__ pval, const int* __restrict__ pidx,
                             int* __restrict__ idxout) {
    int t = blockIdx.x * blockDim.x + threadIdx.x;
    if (t >= NB * NPIX) return;
    int b = t >> 12, i = t & (NPIX - 1);
    float bv = pval[(long)b * NPIX + i];
    int bi = pidx[(long)b * NPIX + i];
#pragma unroll
    for (int jq = 1; jq < 4; jq++) {
        long o = ((long)jq * NB + b) * NPIX + i;
        float v = pval[o];
        int ii = pidx[o];
        if (v < bv || (v == bv && ii < bi)) { bv = v; bi = ii; }
    }
    idxout[t] = bi;
}

// ---------------- gather ----------------
__global__ void gather_kernel(const float* __restrict__ f2, const int* __restrict__ idx,
                              float* __restrict__ out) {
    long t = (long)blockIdx.x * blockDim.x + threadIdx.x;
    if (t >= (long)NB * C3 * NPIX) return;
    int j = (int)(t & (NPIX - 1));
    int c = (int)((t >> 12) & 255);
    int b = (int)(t >> 20);
    int id = idx[(long)b * NPIX + j];
    out[((long)b * 512 + 256 + c) * NPIX + j] = f2[((long)b * C3 + c) * NPIX + id];
}

// ---------------- launch ----------------
extern "C" void kernel_launch(void* const* d_in, const int* in_sizes, int n_in,
                              void* d_out, int out_size) {
    const float* x1 = (const float*)d_in[0];
    const float* x2 = (const float*)d_in[1];
    const float* w1 = (const float*)d_in[2];
    const float* b1 = (const float*)d_in[3];
    const float* w2 = (const float*)d_in[4];
    const float* b2 = (const float*)d_in[5];
    const float* w3 = (const float*)d_in[6];
    const float* b3 = (const float*)d_in[7];
    float* out = (float*)d_out;

    float *T1, *T2, *F2, *B2N, *PVAL;
    int *IDX, *PIDX;
    ull *QD, *Wt2D, *Wt3D;
    cudaGetSymbolAddress((void**)&T1, g_T1);
    cudaGetSymbolAddress((void**)&T2, g_T2);
    cudaGetSymbolAddress((void**)&F2, g_F2);
    cudaGetSymbolAddress((void**)&B2N, g_B2N);
    cudaGetSymbolAddress((void**)&IDX, g_IDX);
    cudaGetSymbolAddress((void**)&Wt2D, g_Wt2D);
    cudaGetSymbolAddress((void**)&Wt3D, g_Wt3D);
    cudaGetSymbolAddress((void**)&PVAL, g_PVAL);
    cudaGetSymbolAddress((void**)&PIDX, g_PIDX);
    cudaGetSymbolAddress((void**)&QD, g_QD);

    cudaFuncSetAttribute(dist_argmin_kernel, cudaFuncAttributeMaxDynamicSharedMemorySize,
                         DSM_TOTAL);

    prep_kernel<<<(C2 * 288 + C3 * 576 + 255) / 256, 256>>>(w2, w3, Wt2D, Wt3D);
    conv1_kernel<<<dim3(NPIX / 256, 8), 256>>>(x1, x2, w1, b1, T1);
    conv_gemm_kernel<64, 4><<<dim3(32, 1, 8), 256>>>(
        T1, C1, Wt2D, 288, C2, b2, T2, (long)C2 * NPIX, T2 + (long)NB * C2 * NPIX,
        (long)C2 * NPIX);
    conv_gemm_kernel<128, 8><<<dim3(32, 2, 8), 256>>>(
        T2, C2, Wt3D, 576, C3, b3, out, (long)512 * NPIX, F2, (long)C3 * NPIX);
    dupq_norm_kernel<<<8192 + 64, 256>>>(out, F2, QD, B2N);
    dist_argmin_kernel<<<dim3(32, 4, NB), 256, DSM_TOTAL>>>(QD, F2, B2N, PVAL, PIDX);
    merge_kernel<<<(NB * NPIX + 255) / 256, 256>>>(PVAL, PIDX, IDX);
    gather_kernel<<<(int)(((long)NB * C3 * NPIX + 255) / 256), 256>>>(F2, IDX, out);
}

// round 11
// speedup vs baseline: 2.3262x; 1.0303x over previous
#include <cuda_runtime.h>
#include <cstdint>

#define HH 64
#define WW 64
#define NPIX 4096
#define NB 4
#define C1 32
#define C2 64
#define C3 256

typedef unsigned long long ull;

__device__ __forceinline__ ull dup2(float v) {
    ull r;
    asm("mov.b64 %0, {%1, %1};" : "=l"(r) : "r"(__float_as_uint(v)));
    return r;
}
__device__ __forceinline__ void ffma2(ull& acc, ull a, ull b) {
    asm("fma.rn.f32x2 %0, %1, %2, %0;" : "+l"(acc) : "l"(a), "l"(b));
}
__device__ __forceinline__ float lo32(ull x) { return __uint_as_float((unsigned int)x); }
__device__ __forceinline__ float hi32(ull x) { return __uint_as_float((unsigned int)(x >> 32)); }
__device__ __forceinline__ uint32_t smem_u32(const void* p) {
    uint32_t a;
    asm("{ .reg .u64 t; cvta.to.shared.u64 t, %1; cvt.u32.u64 %0, t; }" : "=r"(a) : "l"(p));
    return a;
}
#define CP_ASYNC16(dst, src) \
    asm volatile("cp.async.cg.shared.global [%0], [%1], 16;" :: "r"(dst), "l"(src) : "memory")
#define CP_COMMIT() asm volatile("cp.async.commit_group;" ::: "memory")
#define CP_WAIT1() asm volatile("cp.async.wait_group 1;" ::: "memory")
#define CP_WAIT0() asm volatile("cp.async.wait_group 0;" ::: "memory")

// ---------------- static device scratch ----------------
__device__ float g_T1[2 * NB * C1 * NPIX];
__device__ float g_T2[2 * NB * C2 * NPIX];
__device__ __align__(16) float g_IC[2 * NB * 576 * NPIX];  // im2col buffer (75.5 MB)
__device__ float g_F2[NB * C3 * NPIX];
__device__ float g_B2N[NB * NPIX];
__device__ int g_IDX[NB * NPIX];
__device__ __align__(16) ull g_Wt2D[288 * C2];   // dup'd weights [k][co]
__device__ __align__(16) ull g_Wt3D[576 * C3];
__device__ float g_PVAL[4 * NB * NPIX];
__device__ int g_PIDX[4 * NB * NPIX];
__device__ __align__(16) ull g_QD[(long)NB * C3 * NPIX];

// ---------------- prep: transpose + duplicate weights ----------------
__global__ void prep_kernel(const float* __restrict__ w2, const float* __restrict__ w3,
                            ull* __restrict__ Wt2D, ull* __restrict__ Wt3D) {
    int t = blockIdx.x * blockDim.x + threadIdx.x;
    if (t < C2 * 288) {
        int co = t / 288, k = t - co * 288;
        Wt2D[k * C2 + co] = dup2(w2[t]);
    } else {
        int u = t - C2 * 288;
        if (u < C3 * 576) {
            int co = u / 576, k = u - co * 576;
            Wt3D[k * C3 + co] = dup2(w3[u]);
        }
    }
}

// ---------------- conv1 ----------------
__global__ void conv1_kernel(const float* __restrict__ x1, const float* __restrict__ x2,
                             const float* __restrict__ w, const float* __restrict__ bias,
                             float* __restrict__ out) {
    int p = blockIdx.x * blockDim.x + threadIdx.x;
    int z = blockIdx.y;
    if (p >= NPIX) return;
    const float* x = (z >> 2) ? x2 : x1;
    int b = z & 3;
    int y = p >> 6, xx = p & 63;
    const float* xb = x + (long)b * NPIX;
    float in[9];
#pragma unroll
    for (int ky = 0; ky < 3; ky++)
#pragma unroll
        for (int kx = 0; kx < 3; kx++) {
            int yy = y + ky - 1, xc = xx + kx - 1;
            in[ky * 3 + kx] =
                ((unsigned)yy < (unsigned)HH && (unsigned)xc < (unsigned)WW) ? xb[yy * WW + xc] : 0.f;
        }
#pragma unroll 4
    for (int co = 0; co < C1; co++) {
        float acc = bias[co];
#pragma unroll
        for (int t = 0; t < 9; t++) acc += w[co * 9 + t] * in[t];
        out[((long)z * C1 + co) * NPIX + p] = acc;
    }
}

// ---------------- im2col: in [z][CI][NPIX] -> out [z][CI*9][NPIX], zeros at borders ----------------
__global__ void im2col_kernel(const float* __restrict__ in, int CI, float* __restrict__ out) {
    int gk = blockIdx.x;                               // 0..K-1
    int z = blockIdx.y;                                // 0..7
    int n = ((blockIdx.z << 8) + threadIdx.x) << 1;    // 0..4094 step 2
    int K = CI * 9;
    int ci = gk / 9;
    int tap = gk - ci * 9;
    int ky = tap / 3 - 1, kx = tap - (tap / 3) * 3 - 1;
    int y = (n >> 6) + ky;
    int x = (n & 63) + kx;
    const float* row = in + ((long)(z * CI + ci) << 12) + (y << 6);
    float v0 = 0.f, v1 = 0.f;
    if ((unsigned)y < 64u) {
        if ((unsigned)x < 64u) v0 = row[x];
        if ((unsigned)(x + 1) < 64u) v1 = row[x + 1];
    }
    *(float2*)&out[((long)(z * K + gk) << 12) + n] = make_float2(v0, v1);
}

// ---------------- conv-as-GEMM: dup'd-A weights, plain strided B, cp.async 3-stage ----------------
template <int BM, int TM>
__global__ void __launch_bounds__(256, 2)
gemm_conv_kernel(const float* __restrict__ I, int K, const ull* __restrict__ WtD, int CO,
                 const float* __restrict__ bias,
                 float* __restrict__ outA, long sA, float* __restrict__ outB, long sB) {
    extern __shared__ __align__(16) char gsm[];
    const int ABY = 16 * BM * 8;
    uint32_t sbase = smem_u32(gsm);
    int z = blockIdx.z, sel = z >> 2, bb = z & 3;
    float* out = sel ? outB : outA;
    long os = sel ? sB : sA;
    int m0 = blockIdx.y * BM;
    int n0 = blockIdx.x * 128;
    int tid = threadIdx.x, tx = tid & 15, ty = tid >> 4;
    const float* Ib = I + (long)z * K * NPIX;

    ull acc[TM][4];
#pragma unroll
    for (int u = 0; u < TM; u++)
#pragma unroll
        for (int v = 0; v < 4; v++) acc[u][v] = 0ull;

    auto issue = [&](int c, int st) {
        int k0 = c * 16;
        uint32_t da = sbase + (uint32_t)st * ABY;
        uint32_t db = sbase + 3u * ABY + (uint32_t)st * 8192;
        const int NA = BM / 32;
#pragma unroll
        for (int it = 0; it < NA; it++) {
            int e = tid + it * 256;
            int k = e / (BM / 2), c16 = e % (BM / 2);
            const ull* src = WtD + (long)(k0 + k) * CO + m0 + c16 * 2;
            CP_ASYNC16(da + (uint32_t)(k * BM * 8 + c16 * 16), src);
        }
#pragma unroll
        for (int it = 0; it < 2; it++) {
            int e = tid + it * 256;
            int k = e >> 5, c16 = e & 31;
            const float* src = Ib + (long)(k0 + k) * NPIX + n0 + c16 * 4;
            CP_ASYNC16(db + (uint32_t)(k * 512 + c16 * 16), src);
        }
        CP_COMMIT();
    };

    int nch = K / 16;
    issue(0, 0);
    issue(1, 1);

    for (int c = 0; c < nch; c++) {
        int st = c % 3;
        if (c + 1 < nch) CP_WAIT1(); else CP_WAIT0();
        __syncthreads();
        if (c + 2 < nch) issue(c + 2, (c + 2) % 3);
        const ull* AD = (const ull*)(gsm + st * ABY);
        const ull* BsU = (const ull*)(gsm + 3 * ABY + st * 8192);
#pragma unroll
        for (int kk = 0; kk < 16; kk++) {
            ull a2[TM];
#pragma unroll
            for (int h = 0; h < TM / 2; h++) {
                ulonglong2 t = *(const ulonglong2*)&AD[kk * BM + ty * TM + h * 2];
                a2[h * 2] = t.x;
                a2[h * 2 + 1] = t.y;
            }
            ull bq[4];
#pragma unroll
            for (int s = 0; s < 4; s++) bq[s] = BsU[kk * 64 + s * 16 + tx];
#pragma unroll
            for (int u = 0; u < TM; u++)
#pragma unroll
                for (int s = 0; s < 4; s++) ffma2(acc[u][s], a2[u], bq[s]);
        }
    }
#pragma unroll
    for (int u = 0; u < TM; u++) {
        int m = m0 + ty * TM + u;
        float bval = bias[m];
        long base = (long)bb * os + (long)m * NPIX + n0;
#pragma unroll
        for (int s = 0; s < 4; s++) {
            float2 o;
            o.x = lo32(acc[u][s]) + bval;
            o.y = hi32(acc[u][s]) + bval;
            *(float2*)&out[base + s * 32 + tx * 2] = o;
        }
    }
}

// ---------------- fused: Q duplication + key row norms ----------------
__global__ void dupq_norm_kernel(const float* __restrict__ f1out, const float* __restrict__ f2,
                                 ull* __restrict__ QD, float* __restrict__ b2n) {
    int bx = blockIdx.x;
    int tid = threadIdx.x;
    if (bx < 8192) {
        long t2 = ((long)bx * 256 + tid) * 2;
        int b = (int)(t2 >> 20);
        int c = (int)((t2 >> 12) & 255);
        int i = (int)(t2 & 4095);
        float2 v = *(const float2*)&f1out[((long)b * 512 + c) * NPIX + i];
        ull* d = &QD[((long)b * C3 + c) * NPIX + i];
        d[0] = dup2(v.x);
        d[1] = dup2(v.y);
    } else {
        int t = (bx - 8192) * 256 + tid;
        int b = t >> 12, j = t & 4095;
        const float* p = f2 + (long)b * C3 * NPIX + j;
        float s = 0.f;
#pragma unroll 8
        for (int c = 0; c < C3; c++) {
            float v = p[(long)c * NPIX];
            s += v * v;
        }
        b2n[t] = s;
    }
}

// ---------------- dist GEMM + argmin (round-10 proven, at RF roofline) ----------------
#define DSM_A(st) ((st) * 16384)
#define DSM_B(st) (49152 + (st) * 8192)
#define DSM_TOTAL 73728

__global__ void __launch_bounds__(256, 2)
dist_argmin_kernel(const ull* __restrict__ QD, const float* __restrict__ f2,
                   const float* __restrict__ b2n, float* __restrict__ pval,
                   int* __restrict__ pidx) {
    extern __shared__ __align__(16) char dsm[];
    uint32_t sbase = smem_u32(dsm);
    int b = blockIdx.z;
    int jq = blockIdx.y;
    int i0 = blockIdx.x * 128;
    const ull* Qd = QD + (long)b * C3 * NPIX;
    const float* Kf = f2 + (long)b * C3 * NPIX;
    const float* bn = b2n + (long)b * NPIX;
    int tid = threadIdx.x;
    int tx = tid & 15, ty = tid >> 4;

    float bestv[8];
    int besti[8];
#pragma unroll
    for (int u = 0; u < 8; u++) { bestv[u] = 3.4e38f; besti[u] = 0; }

    ull acc[8][4];
#pragma unroll
    for (int u = 0; u < 8; u++)
#pragma unroll
        for (int v = 0; v < 4; v++) acc[u][v] = 0ull;

    auto issue = [&](int c, int st) {
        int k0 = (c & 15) * 16;
        int j0 = jq * 1024 + (c >> 4) * 128;
        uint32_t da = sbase + DSM_A(st);
        uint32_t db = sbase + DSM_B(st);
#pragma unroll
        for (int it = 0; it < 4; it++) {
            int e = tid + it * 256;
            int row = e >> 6, c16 = e & 63;
            const ull* src = Qd + (long)(k0 + row) * NPIX + i0 + c16 * 2;
            CP_ASYNC16(da + (uint32_t)(row * 1024 + c16 * 16), src);
        }
#pragma unroll
        for (int it = 0; it < 2; it++) {
            int e = tid + it * 256;
            int row = e >> 5, c16 = e & 31;
            const float* src = Kf + (long)(k0 + row) * NPIX + j0 + c16 * 4;
            CP_ASYNC16(db + (uint32_t)(row * 512 + c16 * 16), src);
        }
        CP_COMMIT();
    };

    const int NCH = 128;
    issue(0, 0);
    issue(1, 1);

    for (int c = 0; c < NCH; c++) {
        int st = c % 3;
        if (c + 1 < NCH) CP_WAIT1(); else CP_WAIT0();
        __syncthreads();
        if (c + 2 < NCH) issue(c + 2, (c + 2) % 3);
        const ull* AD = (const ull*)(dsm + DSM_A(st));
        const ull* BsU = (const ull*)(dsm + DSM_B(st));
#pragma unroll
        for (int kk = 0; kk < 16; kk++) {
            ull a2[8];
#pragma unroll
            for (int h = 0; h < 4; h++) {
                ulonglong2 t = *(const ulonglong2*)&AD[kk * 128 + ty * 8 + h * 2];
                a2[h * 2] = t.x;
                a2[h * 2 + 1] = t.y;
            }
            ull bq[4];
#pragma unroll
            for (int s = 0; s < 4; s++) bq[s] = BsU[kk * 64 + s * 16 + tx];
#pragma unroll
            for (int u = 0; u < 8; u++)
#pragma unroll
                for (int s = 0; s < 4; s++) ffma2(acc[u][s], a2[u], bq[s]);
        }
        if ((c & 15) == 15) {
            int j0 = jq * 1024 + (c >> 4) * 128;
#pragma unroll
            for (int s = 0; s < 4; s++) {
                int jj = j0 + s * 32 + tx * 2;
                float bj0 = __ldg(&bn[jj]);
                float bj1 = __ldg(&bn[jj + 1]);
#pragma unroll
                for (int u = 0; u < 8; u++) {
                    ull A = acc[u][s];
                    float d0 = bj0 - 2.f * lo32(A);
                    if (d0 < bestv[u]) { bestv[u] = d0; besti[u] = jj; }
                    float d1 = bj1 - 2.f * hi32(A);
                    if (d1 < bestv[u]) { bestv[u] = d1; besti[u] = jj + 1; }
                    acc[u][s] = 0ull;
                }
            }
        }
    }
    __syncthreads();
    float* rv = (float*)dsm;
    int* ri = (int*)(dsm + 8192);
#pragma unroll
    for (int u = 0; u < 8; u++) {
        rv[tx * 128 + ty * 8 + u] = bestv[u];
        ri[tx * 128 + ty * 8 + u] = besti[u];
    }
    __syncthreads();
    if (tid < 128) {
        float bv = rv[tid];
        int bi = ri[tid];
#pragma unroll
        for (int t = 1; t < 16; t++) {
            float v = rv[t * 128 + tid];
            int ii = ri[t * 128 + tid];
            if (v < bv || (v == bv && ii < bi)) { bv = v; bi = ii; }
        }
        long o = ((long)jq * NB + b) * NPIX + i0 + tid;
        pval[o] = bv;
        pidx[o] = bi;
    }
}

// ---------------- merge 4 j-quarter candidates ----------------
__global__ void merge_kernel(const float* __restrict__ pval, const int* __restrict__ pidx,
                             int* __restrict__ idxout) {
    int t = blockIdx.x * blockDim.x + threadIdx.x;
    if (t >= NB * NPIX) return;
    int b = t >> 12, i = t & (NPIX - 1);
    float bv = pval[(long)b * NPIX + i];
    int bi = pidx[(long)b * NPIX + i];
#pragma unroll
    for (int jq = 1; jq < 4; jq++) {
        long o = ((long)jq * NB + b) * NPIX + i;
        float v = pval[o];
        int ii = pidx[o];
        if (v < bv || (v == bv && ii < bi)) { bv = v; bi = ii; }
    }
    idxout[t] = bi;
}

// ---------------- gather ----------------
__global__ void gather_kernel(const float* __restrict__ f2, const int* __restrict__ idx,
                              float* __restrict__ out) {
    long t = (long)blockIdx.x * blockDim.x + threadIdx.x;
    if (t >= (long)NB * C3 * NPIX) return;
    int j = (int)(t & (NPIX - 1));
    int c = (int)((t >> 12) & 255);
    int b = (int)(t >> 20);
    int id = idx[(long)b * NPIX + j];
    out[((long)b * 512 + 256 + c) * NPIX + j] = f2[((long)b * C3 + c) * NPIX + id];
}

// ---------------- launch ----------------
extern "C" void kernel_launch(void* const* d_in, const int* in_sizes, int n_in,
                              void* d_out, int out_size) {
    const float* x1 = (const float*)d_in[0];
    const float* x2 = (const float*)d_in[1];
    const float* w1 = (const float*)d_in[2];
    const float* b1 = (const float*)d_in[3];
    const float* w2 = (const float*)d_in[4];
    const float* b2 = (const float*)d_in[5];
    const float* w3 = (const float*)d_in[6];
    const float* b3 = (const float*)d_in[7];
    float* out = (float*)d_out;

    float *T1, *T2, *IC, *F2, *B2N, *PVAL;
    int *IDX, *PIDX;
    ull *QD, *Wt2D, *Wt3D;
    cudaGetSymbolAddress((void**)&T1, g_T1);
    cudaGetSymbolAddress((void**)&T2, g_T2);
    cudaGetSymbolAddress((void**)&IC, g_IC);
    cudaGetSymbolAddress((void**)&F2, g_F2);
    cudaGetSymbolAddress((void**)&B2N, g_B2N);
    cudaGetSymbolAddress((void**)&IDX, g_IDX);
    cudaGetSymbolAddress((void**)&Wt2D, g_Wt2D);
    cudaGetSymbolAddress((void**)&Wt3D, g_Wt3D);
    cudaGetSymbolAddress((void**)&PVAL, g_PVAL);
    cudaGetSymbolAddress((void**)&PIDX, g_PIDX);
    cudaGetSymbolAddress((void**)&QD, g_QD);

    cudaFuncSetAttribute(dist_argmin_kernel, cudaFuncAttributeMaxDynamicSharedMemorySize,
                         DSM_TOTAL);
    cudaFuncSetAttribute(gemm_conv_kernel<64, 4>, cudaFuncAttributeMaxDynamicSharedMemorySize,
                         3 * (16 * 64 * 8) + 3 * 8192);
    cudaFuncSetAttribute(gemm_conv_kernel<128, 8>, cudaFuncAttributeMaxDynamicSharedMemorySize,
                         3 * (16 * 128 * 8) + 3 * 8192);

    prep_kernel<<<(C2 * 288 + C3 * 576 + 255) / 256, 256>>>(w2, w3, Wt2D, Wt3D);
    conv1_kernel<<<dim3(NPIX / 256, 8), 256>>>(x1, x2, w1, b1, T1);
    im2col_kernel<<<dim3(288, 8, 8), 256>>>(T1, C1, IC);
    gemm_conv_kernel<64, 4><<<dim3(32, 1, 8), 256, 3 * (16 * 64 * 8) + 3 * 8192>>>(
        IC, 288, Wt2D, C2, b2, T2, (long)C2 * NPIX, T2 + (long)NB * C2 * NPIX, (long)C2 * NPIX);
    im2col_kernel<<<dim3(576, 8, 8), 256>>>(T2, C2, IC);
    gemm_conv_kernel<128, 8><<<dim3(32, 2, 8), 256, 3 * (16 * 128 * 8) + 3 * 8192>>>(
        IC, 576, Wt3D, C3, b3, out, (long)512 * NPIX, F2, (long)C3 * NPIX);
    dupq_norm_kernel<<<8192 + 64, 256>>>(out, F2, QD, B2N);
    dist_argmin_kernel<<<dim3(32, 4, NB), 256, DSM_TOTAL>>>(QD, F2, B2N, PVAL, PIDX);
    merge_kernel<<<(NB * NPIX + 255) / 256, 256>>>(PVAL, PIDX, IDX);
    gather_kernel<<<(int)(((long)NB * C3 * NPIX + 255) / 256), 256>>>(F2, IDX, out);
}

// round 12
// speedup vs baseline: 2.9115x; 1.2516x over previous
#include <cuda_runtime.h>
#include <cuda_bf16.h>
#include <cstdint>

#define HH 64
#define WW 64
#define NPIX 4096
#define NB 4
#define C1 32
#define C2 64
#define C3 256

typedef unsigned long long ull;

__device__ __forceinline__ ull dup2(float v) {
    ull r;
    asm("mov.b64 %0, {%1, %1};" : "=l"(r) : "r"(__float_as_uint(v)));
    return r;
}
__device__ __forceinline__ void ffma2(ull& acc, ull a, ull b) {
    asm("fma.rn.f32x2 %0, %1, %2, %0;" : "+l"(acc) : "l"(a), "l"(b));
}
__device__ __forceinline__ float lo32(ull x) { return __uint_as_float((unsigned int)x); }
__device__ __forceinline__ float hi32(ull x) { return __uint_as_float((unsigned int)(x >> 32)); }
__device__ __forceinline__ uint32_t smem_u32(const void* p) {
    uint32_t a;
    asm("{ .reg .u64 t; cvta.to.shared.u64 t, %1; cvt.u32.u64 %0, t; }" : "=r"(a) : "l"(p));
    return a;
}
#define CP_ASYNC16(dst, src) \
    asm volatile("cp.async.cg.shared.global [%0], [%1], 16;" :: "r"(dst), "l"(src) : "memory")
#define CP_COMMIT() asm volatile("cp.async.commit_group;" ::: "memory")
#define CP_WAIT1() asm volatile("cp.async.wait_group 1;" ::: "memory")
#define CP_WAIT0() asm volatile("cp.async.wait_group 0;" ::: "memory")
#define LDSM_X4(r0, r1, r2, r3, a) \
    asm volatile("ldmatrix.sync.aligned.m8n8.x4.shared.b16 {%0,%1,%2,%3}, [%4];" \
        : "=r"(r0), "=r"(r1), "=r"(r2), "=r"(r3) : "r"(a))
#define LDSM_X2(r0, r1, a) \
    asm volatile("ldmatrix.sync.aligned.m8n8.x2.shared.b16 {%0,%1}, [%2];" \
        : "=r"(r0), "=r"(r1) : "r"(a))
#define MMA_BF16(d, a, bf) \
    asm volatile( \
        "mma.sync.aligned.m16n8k16.row.col.f32.bf16.bf16.f32 " \
        "{%0,%1,%2,%3}, {%4,%5,%6,%7}, {%8,%9}, {%0,%1,%2,%3};" \
        : "+f"((d)[0]), "+f"((d)[1]), "+f"((d)[2]), "+f"((d)[3]) \
        : "r"((a)[0]), "r"((a)[1]), "r"((a)[2]), "r"((a)[3]), "r"((bf)[0]), "r"((bf)[1]))

// ---------------- static device scratch ----------------
__device__ float g_T1[2 * NB * C1 * NPIX];
__device__ float g_T2[2 * NB * C2 * NPIX];
__device__ __align__(16) float g_IC[2 * NB * 576 * NPIX];
__device__ float g_F2[NB * C3 * NPIX];
__device__ float g_B2N[NB * NPIX];
__device__ int g_IDX[NB * NPIX];
__device__ __align__(16) ull g_Wt2D[288 * C2];
__device__ __align__(16) ull g_Wt3D[576 * C3];
__device__ float g_PVAL[32 * NB * NPIX];
__device__ int g_PIDX[32 * NB * NPIX];
__device__ __align__(16) __nv_bfloat16 g_QS[(long)NB * NPIX * 768];
__device__ __align__(16) __nv_bfloat16 g_KS[(long)NB * NPIX * 768];

// ---------------- prep: transpose + duplicate weights ----------------
__global__ void prep_kernel(const float* __restrict__ w2, const float* __restrict__ w3,
                            ull* __restrict__ Wt2D, ull* __restrict__ Wt3D) {
    int t = blockIdx.x * blockDim.x + threadIdx.x;
    if (t < C2 * 288) {
        int co = t / 288, k = t - co * 288;
        Wt2D[k * C2 + co] = dup2(w2[t]);
    } else {
        int u = t - C2 * 288;
        if (u < C3 * 576) {
            int co = u / 576, k = u - co * 576;
            Wt3D[k * C3 + co] = dup2(w3[u]);
        }
    }
}

// ---------------- conv1 ----------------
__global__ void conv1_kernel(const float* __restrict__ x1, const float* __restrict__ x2,
                             const float* __restrict__ w, const float* __restrict__ bias,
                             float* __restrict__ out) {
    int p = blockIdx.x * blockDim.x + threadIdx.x;
    int z = blockIdx.y;
    if (p >= NPIX) return;
    const float* x = (z >> 2) ? x2 : x1;
    int b = z & 3;
    int y = p >> 6, xx = p & 63;
    const float* xb = x + (long)b * NPIX;
    float in[9];
#pragma unroll
    for (int ky = 0; ky < 3; ky++)
#pragma unroll
        for (int kx = 0; kx < 3; kx++) {
            int yy = y + ky - 1, xc = xx + kx - 1;
            in[ky * 3 + kx] =
                ((unsigned)yy < (unsigned)HH && (unsigned)xc < (unsigned)WW) ? xb[yy * WW + xc] : 0.f;
        }
#pragma unroll 4
    for (int co = 0; co < C1; co++) {
        float acc = bias[co];
#pragma unroll
        for (int t = 0; t < 9; t++) acc += w[co * 9 + t] * in[t];
        out[((long)z * C1 + co) * NPIX + p] = acc;
    }
}

// ---------------- im2col ----------------
__global__ void im2col_kernel(const float* __restrict__ in, int CI, float* __restrict__ out) {
    int gk = blockIdx.x;
    int z = blockIdx.y;
    int n = ((blockIdx.z << 8) + threadIdx.x) << 1;
    int K = CI * 9;
    int ci = gk / 9;
    int tap = gk - ci * 9;
    int ky = tap / 3 - 1, kx = tap - (tap / 3) * 3 - 1;
    int y = (n >> 6) + ky;
    int x = (n & 63) + kx;
    const float* row = in + ((long)(z * CI + ci) << 12) + (y << 6);
    float v0 = 0.f, v1 = 0.f;
    if ((unsigned)y < 64u) {
        if ((unsigned)x < 64u) v0 = row[x];
        if ((unsigned)(x + 1) < 64u) v1 = row[x + 1];
    }
    *(float2*)&out[((long)(z * K + gk) << 12) + n] = make_float2(v0, v1);
}

// ---------------- conv-as-GEMM (round-11 proven) ----------------
template <int BM, int TM>
__global__ void __launch_bounds__(256, 2)
gemm_conv_kernel(const float* __restrict__ I, int K, const ull* __restrict__ WtD, int CO,
                 const float* __restrict__ bias,
                 float* __restrict__ outA, long sA, float* __restrict__ outB, long sB) {
    extern __shared__ __align__(16) char gsm[];
    const int ABY = 16 * BM * 8;
    uint32_t sbase = smem_u32(gsm);
    int z = blockIdx.z, sel = z >> 2, bb = z & 3;
    float* out = sel ? outB : outA;
    long os = sel ? sB : sA;
    int m0 = blockIdx.y * BM;
    int n0 = blockIdx.x * 128;
    int tid = threadIdx.x, tx = tid & 15, ty = tid >> 4;
    const float* Ib = I + (long)z * K * NPIX;

    ull acc[TM][4];
#pragma unroll
    for (int u = 0; u < TM; u++)
#pragma unroll
        for (int v = 0; v < 4; v++) acc[u][v] = 0ull;

    auto issue = [&](int c, int st) {
        int k0 = c * 16;
        uint32_t da = sbase + (uint32_t)st * ABY;
        uint32_t db = sbase + 3u * ABY + (uint32_t)st * 8192;
        const int NA = BM / 32;
#pragma unroll
        for (int it = 0; it < NA; it++) {
            int e = tid + it * 256;
            int k = e / (BM / 2), c16 = e % (BM / 2);
            const ull* src = WtD + (long)(k0 + k) * CO + m0 + c16 * 2;
            CP_ASYNC16(da + (uint32_t)(k * BM * 8 + c16 * 16), src);
        }
#pragma unroll
        for (int it = 0; it < 2; it++) {
            int e = tid + it * 256;
            int k = e >> 5, c16 = e & 31;
            const float* src = Ib + (long)(k0 + k) * NPIX + n0 + c16 * 4;
            CP_ASYNC16(db + (uint32_t)(k * 512 + c16 * 16), src);
        }
        CP_COMMIT();
    };

    int nch = K / 16;
    issue(0, 0);
    issue(1, 1);

    for (int c = 0; c < nch; c++) {
        int st = c % 3;
        if (c + 1 < nch) CP_WAIT1(); else CP_WAIT0();
        __syncthreads();
        if (c + 2 < nch) issue(c + 2, (c + 2) % 3);
        const ull* AD = (const ull*)(gsm + st * ABY);
        const ull* BsU = (const ull*)(gsm + 3 * ABY + st * 8192);
#pragma unroll
        for (int kk = 0; kk < 16; kk++) {
            ull a2[TM];
#pragma unroll
            for (int h = 0; h < TM / 2; h++) {
                ulonglong2 t = *(const ulonglong2*)&AD[kk * BM + ty * TM + h * 2];
                a2[h * 2] = t.x;
                a2[h * 2 + 1] = t.y;
            }
            ull bq[4];
#pragma unroll
            for (int s = 0; s < 4; s++) bq[s] = BsU[kk * 64 + s * 16 + tx];
#pragma unroll
            for (int u = 0; u < TM; u++)
#pragma unroll
                for (int s = 0; s < 4; s++) ffma2(acc[u][s], a2[u], bq[s]);
        }
    }
#pragma unroll
    for (int u = 0; u < TM; u++) {
        int m = m0 + ty * TM + u;
        float bval = bias[m];
        long base = (long)bb * os + (long)m * NPIX + n0;
#pragma unroll
        for (int s = 0; s < 4; s++) {
            float2 o;
            o.x = lo32(acc[u][s]) + bval;
            o.y = hi32(acc[u][s]) + bval;
            *(float2*)&out[base + s * 32 + tx * 2] = o;
        }
    }
}

// ---------------- split to bf16 h/m/l stacks (768 k each) + key norms ----------------
__global__ void split_kernel(const float* __restrict__ f1out, const float* __restrict__ f2,
                             __nv_bfloat16* __restrict__ QS, __nv_bfloat16* __restrict__ KS,
                             float* __restrict__ b2n) {
    __shared__ __nv_bfloat16 sh[3][64][64];
    __shared__ float snorm[256];
    int n0 = blockIdx.x * 64;
    int src = blockIdx.y;
    int b = blockIdx.z;
    const float* f = src ? (f2 + (long)b * C3 * NPIX) : (f1out + (long)b * 512 * NPIX);
    __nv_bfloat16* dst = (src ? KS : QS) + (long)b * NPIX * 768;
    int tid = threadIdx.x;
    int nl = tid & 63, cq = tid >> 6;
    float nacc = 0.f;
    for (int cc = 0; cc < 4; cc++) {
        int cbase = cc * 64;
#pragma unroll
        for (int r = 0; r < 16; r++) {
            int cl = cq + r * 4;
            float x = f[(long)(cbase + cl) * NPIX + n0 + nl];
            __nv_bfloat16 h = __float2bfloat16(x);
            float rr = x - __bfloat162float(h);
            __nv_bfloat16 m = __float2bfloat16(rr);
            float r2 = rr - __bfloat162float(m);
            sh[0][cl][nl] = h;
            sh[1][cl][nl] = m;
            sh[2][cl][nl] = __float2bfloat16(r2);
            nacc += x * x;
        }
        __syncthreads();
        int nl2 = tid >> 2;
        int cg = (tid & 3) * 16;
#pragma unroll
        for (int s = 0; s < 3; s++) {
            __nv_bfloat16* drow = dst + (long)(n0 + nl2) * 768 + s * 256 + cbase + cg;
#pragma unroll
            for (int j = 0; j < 16; j++) drow[j] = sh[s][cg + j][nl2];
        }
        __syncthreads();
    }
    if (src == 1) {
        snorm[tid] = nacc;
        __syncthreads();
        if (tid < 64)
            b2n[(long)b * NPIX + n0 + tid] =
                snorm[tid] + snorm[tid + 64] + snorm[tid + 128] + snorm[tid + 192];
    }
}

// ---------------- dist GEMM + argmin via mma.sync bf16 (HMMA) ----------------
// 128i x 128j per CTA, K=6 products x 256 streamed as 24 chunks of 64.
#define MSTB 32768
#define MSM_TOTAL (3 * MSTB)

__global__ void __launch_bounds__(256, 2)
dist_mma_kernel(const __nv_bfloat16* __restrict__ QS, const __nv_bfloat16* __restrict__ KS,
                const float* __restrict__ b2n, float* __restrict__ pval,
                int* __restrict__ pidx) {
    extern __shared__ __align__(16) char dsm[];
    uint32_t sb = smem_u32(dsm);
    int b = blockIdx.z;
    int jq = blockIdx.y;
    int j0 = jq * 128;
    int i0 = blockIdx.x * 128;
    int tid = threadIdx.x;
    int lane = tid & 31, wid = tid >> 5;
    int wm = wid & 1, wn = wid >> 1;  // 2 m-halves x 4 n-quarters

    const __nv_bfloat16* Qb = QS + (long)(b * NPIX + i0) * 768;
    const __nv_bfloat16* Kb = KS + (long)(b * NPIX + j0) * 768;
    const float* bn = b2n + (long)b * NPIX;

    float acc[4][4][4];
#pragma unroll
    for (int mt = 0; mt < 4; mt++)
#pragma unroll
        for (int nt = 0; nt < 4; nt++)
#pragma unroll
            for (int q = 0; q < 4; q++) acc[mt][nt][q] = 0.f;

    const int segQ[6] = {0, 1, 2, 0, 0, 1};
    const int segK[6] = {0, 0, 0, 1, 2, 1};

    auto issue = [&](int c, int st) {
        int prod = c >> 2, sub = c & 3;
        int kq = segQ[prod] * 256 + sub * 64;
        int kk = segK[prod] * 256 + sub * 64;
        uint32_t da = sb + (uint32_t)st * MSTB;
        uint32_t db = da + 16384;
#pragma unroll
        for (int it = 0; it < 4; it++) {
            int e = tid + it * 256;
            int row = e >> 3, k8 = e & 7;
            uint32_t soff = (uint32_t)(row * 128 + ((k8 ^ (row & 7)) << 4));
            CP_ASYNC16(da + soff, Qb + (long)row * 768 + kq + k8 * 8);
            CP_ASYNC16(db + soff, Kb + (long)row * 768 + kk + k8 * 8);
        }
        CP_COMMIT();
    };

    const int NCH = 24;
    issue(0, 0);
    issue(1, 1);

    for (int c = 0; c < NCH; c++) {
        int st = c % 3;
        if (c + 1 < NCH) CP_WAIT1(); else CP_WAIT0();
        __syncthreads();
        if (c + 2 < NCH) issue(c + 2, (c + 2) % 3);
        uint32_t Ab = sb + (uint32_t)st * MSTB;
        uint32_t Bb = Ab + 16384;
#pragma unroll
        for (int ks = 0; ks < 4; ks++) {
            uint32_t af[4][4];
#pragma unroll
            for (int mt = 0; mt < 4; mt++) {
                int row = wm * 64 + mt * 16 + (lane & 15);
                int k8 = ks * 2 + (lane >> 4);
                LDSM_X4(af[mt][0], af[mt][1], af[mt][2], af[mt][3],
                        Ab + (uint32_t)(row * 128 + ((k8 ^ (row & 7)) << 4)));
            }
            uint32_t bf[4][2];
#pragma unroll
            for (int nt = 0; nt < 4; nt++) {
                int rowb = wn * 32 + nt * 8 + (lane & 7);
                int k8 = ks * 2 + ((lane >> 3) & 1);
                LDSM_X2(bf[nt][0], bf[nt][1],
                        Bb + (uint32_t)(rowb * 128 + ((k8 ^ (rowb & 7)) << 4)));
            }
#pragma unroll
            for (int mt = 0; mt < 4; mt++)
#pragma unroll
                for (int nt = 0; nt < 4; nt++) MMA_BF16(acc[mt][nt], af[mt], bf[nt]);
        }
    }

    // epilogue: dist = bn[j] - 2*cross, running argmin (first-index ties)
    float bnv[4][2];
#pragma unroll
    for (int nt = 0; nt < 4; nt++) {
        int jj = j0 + wn * 32 + nt * 8 + (lane & 3) * 2;
        bnv[nt][0] = __ldg(&bn[jj]);
        bnv[nt][1] = __ldg(&bn[jj + 1]);
    }
    float bvA[4], bvB[4];
    int biA[4], biB[4];
#pragma unroll
    for (int mt = 0; mt < 4; mt++) {
        bvA[mt] = 3.4e38f; biA[mt] = 0;
        bvB[mt] = 3.4e38f; biB[mt] = 0;
#pragma unroll
        for (int nt = 0; nt < 4; nt++)
#pragma unroll
            for (int p = 0; p < 2; p++) {
                int j = j0 + wn * 32 + nt * 8 + (lane & 3) * 2 + p;
                float dA = bnv[nt][p] - 2.f * acc[mt][nt][p];
                if (dA < bvA[mt]) { bvA[mt] = dA; biA[mt] = j; }
                float dB = bnv[nt][p] - 2.f * acc[mt][nt][2 + p];
                if (dB < bvB[mt]) { bvB[mt] = dB; biB[mt] = j; }
            }
        // quad reduction across lanes sharing the row (lane&3)
#pragma unroll
        for (int m = 1; m <= 2; m <<= 1) {
            float ov = __shfl_xor_sync(0xffffffffu, bvA[mt], m);
            int oi = __shfl_xor_sync(0xffffffffu, biA[mt], m);
            if (ov < bvA[mt] || (ov == bvA[mt] && oi < biA[mt])) { bvA[mt] = ov; biA[mt] = oi; }
            ov = __shfl_xor_sync(0xffffffffu, bvB[mt], m);
            oi = __shfl_xor_sync(0xffffffffu, biB[mt], m);
            if (ov < bvB[mt] || (ov == bvB[mt] && oi < biB[mt])) { bvB[mt] = ov; biB[mt] = oi; }
        }
    }
    __syncthreads();  // all mma/ldsm done; safe to reuse stage smem
    float* rv = (float*)dsm;          // [4 wn][128 rows]
    int* ri = (int*)(dsm + 2048);
    if ((lane & 3) == 0) {
#pragma unroll
        for (int mt = 0; mt < 4; mt++) {
            int r = wm * 64 + mt * 16 + (lane >> 2);
            rv[wn * 128 + r] = bvA[mt];
            ri[wn * 128 + r] = biA[mt];
            rv[wn * 128 + r + 8] = bvB[mt];
            ri[wn * 128 + r + 8] = biB[mt];
        }
    }
    __syncthreads();
    if (tid < 128) {
        float bv = rv[tid];
        int bi = ri[tid];
#pragma unroll
        for (int w = 1; w < 4; w++) {
            float v = rv[w * 128 + tid];
            int ii = ri[w * 128 + tid];
            if (v < bv || (v == bv && ii < bi)) { bv = v; bi = ii; }
        }
        long o = ((long)(jq * NB + b) << 12) + i0 + tid;
        pval[o] = bv;
        pidx[o] = bi;
    }
}

// ---------------- merge 32 j-tile candidates ----------------
__global__ void merge_kernel(const float* __restrict__ pval, const int* __restrict__ pidx,
                             int* __restrict__ idxout) {
    int t = blockIdx.x * blockDim.x + threadIdx.x;
    if (t >= NB * NPIX) return;
    int b = t >> 12, i = t & (NPIX - 1);
    float bv = 3.4e38f;
    int bi = 0;
#pragma unroll 4
    for (int jq = 0; jq < 32; jq++) {
        long o = ((long)(jq * NB + b) << 12) + i;
        float v = pval[o];
        int ii = pidx[o];
        if (v < bv || (v == bv && ii < bi)) { bv = v; bi = ii; }
    }
    idxout[t] = bi;
}

// ---------------- gather ----------------
__global__ void gather_kernel(const float* __restrict__ f2, const int* __restrict__ idx,
                              float* __restrict__ out) {
    long t = (long)blockIdx.x * blockDim.x + threadIdx.x;
    if (t >= (long)NB * C3 * NPIX) return;
    int j = (int)(t & (NPIX - 1));
    int c = (int)((t >> 12) & 255);
    int b = (int)(t >> 20);
    int id = idx[(long)b * NPIX + j];
    out[((long)b * 512 + 256 + c) * NPIX + j] = f2[((long)b * C3 + c) * NPIX + id];
}

// ---------------- launch ----------------
extern "C" void kernel_launch(void* const* d_in, const int* in_sizes, int n_in,
                              void* d_out, int out_size) {
    const float* x1 = (const float*)d_in[0];
    const float* x2 = (const float*)d_in[1];
    const float* w1 = (const float*)d_in[2];
    const float* b1 = (const float*)d_in[3];
    const float* w2 = (const float*)d_in[4];
    const float* b2 = (const float*)d_in[5];
    const float* w3 = (const float*)d_in[6];
    const float* b3 = (const float*)d_in[7];
    float* out = (float*)d_out;

    float *T1, *T2, *IC, *F2, *B2N, *PVAL;
    int *IDX, *PIDX;
    ull *Wt2D, *Wt3D;
    __nv_bfloat16 *QS, *KS;
    cudaGetSymbolAddress((void**)&T1, g_T1);
    cudaGetSymbolAddress((void**)&T2, g_T2);
    cudaGetSymbolAddress((void**)&IC, g_IC);
    cudaGetSymbolAddress((void**)&F2, g_F2);
    cudaGetSymbolAddress((void**)&B2N, g_B2N);
    cudaGetSymbolAddress((void**)&IDX, g_IDX);
    cudaGetSymbolAddress((void**)&Wt2D, g_Wt2D);
    cudaGetSymbolAddress((void**)&Wt3D, g_Wt3D);
    cudaGetSymbolAddress((void**)&PVAL, g_PVAL);
    cudaGetSymbolAddress((void**)&PIDX, g_PIDX);
    cudaGetSymbolAddress((void**)&QS, g_QS);
    cudaGetSymbolAddress((void**)&KS, g_KS);

    cudaFuncSetAttribute(dist_mma_kernel, cudaFuncAttributeMaxDynamicSharedMemorySize,
                         MSM_TOTAL);
    cudaFuncSetAttribute(gemm_conv_kernel<64, 4>, cudaFuncAttributeMaxDynamicSharedMemorySize,
                         3 * (16 * 64 * 8) + 3 * 8192);
    cudaFuncSetAttribute(gemm_conv_kernel<128, 8>, cudaFuncAttributeMaxDynamicSharedMemorySize,
                         3 * (16 * 128 * 8) + 3 * 8192);

    prep_kernel<<<(C2 * 288 + C3 * 576 + 255) / 256, 256>>>(w2, w3, Wt2D, Wt3D);
    conv1_kernel<<<dim3(NPIX / 256, 8), 256>>>(x1, x2, w1, b1, T1);
    im2col_kernel<<<dim3(288, 8, 8), 256>>>(T1, C1, IC);
    gemm_conv_kernel<64, 4><<<dim3(32, 1, 8), 256, 3 * (16 * 64 * 8) + 3 * 8192>>>(
        IC, 288, Wt2D, C2, b2, T2, (long)C2 * NPIX, T2 + (long)NB * C2 * NPIX, (long)C2 * NPIX);
    im2col_kernel<<<dim3(576, 8, 8), 256>>>(T2, C2, IC);
    gemm_conv_kernel<128, 8><<<dim3(32, 2, 8), 256, 3 * (16 * 128 * 8) + 3 * 8192>>>(
        IC, 576, Wt3D, C3, b3, out, (long)512 * NPIX, F2, (long)C3 * NPIX);
    split_kernel<<<dim3(NPIX / 64, 2, NB), 256>>>(out, F2, QS, KS, B2N);
    dist_mma_kernel<<<dim3(32, 32, NB), 256, MSM_TOTAL>>>(QS, KS, B2N, PVAL, PIDX);
    merge_kernel<<<(NB * NPIX + 255) / 256, 256>>>(PVAL, PIDX, IDX);
    gather_kernel<<<(int)(((long)NB * C3 * NPIX + 255) / 256), 256>>>(F2, IDX, out);
}

// round 13
// speedup vs baseline: 3.0281x; 1.0400x over previous
#include <cuda_runtime.h>
#include <cuda_bf16.h>
#include <cstdint>

#define HH 64
#define WW 64
#define NPIX 4096
#define NB 4
#define C1 32
#define C2 64
#define C3 256

typedef unsigned long long ull;

__device__ __forceinline__ ull dup2(float v) {
    ull r;
    asm("mov.b64 %0, {%1, %1};" : "=l"(r) : "r"(__float_as_uint(v)));
    return r;
}
__device__ __forceinline__ void ffma2(ull& acc, ull a, ull b) {
    asm("fma.rn.f32x2 %0, %1, %2, %0;" : "+l"(acc) : "l"(a), "l"(b));
}
__device__ __forceinline__ float lo32(ull x) { return __uint_as_float((unsigned int)x); }
__device__ __forceinline__ float hi32(ull x) { return __uint_as_float((unsigned int)(x >> 32)); }
__device__ __forceinline__ uint32_t smem_u32(const void* p) {
    uint32_t a;
    asm("{ .reg .u64 t; cvta.to.shared.u64 t, %1; cvt.u32.u64 %0, t; }" : "=r"(a) : "l"(p));
    return a;
}
#define CP_ASYNC16(dst, src) \
    asm volatile("cp.async.cg.shared.global [%0], [%1], 16;" :: "r"(dst), "l"(src) : "memory")
#define CP_COMMIT() asm volatile("cp.async.commit_group;" ::: "memory")
#define CP_WAIT1() asm volatile("cp.async.wait_group 1;" ::: "memory")
#define CP_WAIT0() asm volatile("cp.async.wait_group 0;" ::: "memory")
#define LDSM_X4(r0, r1, r2, r3, a) \
    asm volatile("ldmatrix.sync.aligned.m8n8.x4.shared.b16 {%0,%1,%2,%3}, [%4];" \
        : "=r"(r0), "=r"(r1), "=r"(r2), "=r"(r3) : "r"(a))
#define LDSM_X2(r0, r1, a) \
    asm volatile("ldmatrix.sync.aligned.m8n8.x2.shared.b16 {%0,%1}, [%2];" \
        : "=r"(r0), "=r"(r1) : "r"(a))
#define MMA_BF16(d, a, bf) \
    asm volatile( \
        "mma.sync.aligned.m16n8k16.row.col.f32.bf16.bf16.f32 " \
        "{%0,%1,%2,%3}, {%4,%5,%6,%7}, {%8,%9}, {%0,%1,%2,%3};" \
        : "+f"((d)[0]), "+f"((d)[1]), "+f"((d)[2]), "+f"((d)[3]) \
        : "r"((a)[0]), "r"((a)[1]), "r"((a)[2]), "r"((a)[3]), "r"((bf)[0]), "r"((bf)[1]))

// ---------------- static device scratch ----------------
__device__ float g_T1[2 * NB * C1 * NPIX];
__device__ float g_T2[2 * NB * C2 * NPIX];
__device__ __align__(16) float g_IC[2 * NB * 576 * NPIX];
__device__ float g_F2[NB * C3 * NPIX];
__device__ float g_B2N[NB * NPIX];
__device__ int g_IDX[NB * NPIX];
__device__ __align__(16) ull g_Wt2D[288 * C2];
__device__ __align__(16) ull g_Wt3D[576 * C3];
__device__ float g_PVAL[32 * NB * NPIX];
__device__ int g_PIDX[32 * NB * NPIX];
__device__ __align__(16) __nv_bfloat16 g_QS[(long)NB * NPIX * 768];
__device__ __align__(16) __nv_bfloat16 g_KS[(long)NB * NPIX * 768];

// ---------------- prep: transpose + duplicate weights ----------------
__global__ void prep_kernel(const float* __restrict__ w2, const float* __restrict__ w3,
                            ull* __restrict__ Wt2D, ull* __restrict__ Wt3D) {
    int t = blockIdx.x * blockDim.x + threadIdx.x;
    if (t < C2 * 288) {
        int co = t / 288, k = t - co * 288;
        Wt2D[k * C2 + co] = dup2(w2[t]);
    } else {
        int u = t - C2 * 288;
        if (u < C3 * 576) {
            int co = u / 576, k = u - co * 576;
            Wt3D[k * C3 + co] = dup2(w3[u]);
        }
    }
}

// ---------------- conv1 ----------------
__global__ void conv1_kernel(const float* __restrict__ x1, const float* __restrict__ x2,
                             const float* __restrict__ w, const float* __restrict__ bias,
                             float* __restrict__ out) {
    int p = blockIdx.x * blockDim.x + threadIdx.x;
    int z = blockIdx.y;
    if (p >= NPIX) return;
    const float* x = (z >> 2) ? x2 : x1;
    int b = z & 3;
    int y = p >> 6, xx = p & 63;
    const float* xb = x + (long)b * NPIX;
    float in[9];
#pragma unroll
    for (int ky = 0; ky < 3; ky++)
#pragma unroll
        for (int kx = 0; kx < 3; kx++) {
            int yy = y + ky - 1, xc = xx + kx - 1;
            in[ky * 3 + kx] =
                ((unsigned)yy < (unsigned)HH && (unsigned)xc < (unsigned)WW) ? xb[yy * WW + xc] : 0.f;
        }
#pragma unroll 4
    for (int co = 0; co < C1; co++) {
        float acc = bias[co];
#pragma unroll
        for (int t = 0; t < 9; t++) acc += w[co * 9 + t] * in[t];
        out[((long)z * C1 + co) * NPIX + p] = acc;
    }
}

// ---------------- im2col ----------------
__global__ void im2col_kernel(const float* __restrict__ in, int CI, float* __restrict__ out) {
    int gk = blockIdx.x;
    int z = blockIdx.y;
    int n = ((blockIdx.z << 8) + threadIdx.x) << 1;
    int K = CI * 9;
    int ci = gk / 9;
    int tap = gk - ci * 9;
    int ky = tap / 3 - 1, kx = tap - (tap / 3) * 3 - 1;
    int y = (n >> 6) + ky;
    int x = (n & 63) + kx;
    const float* row = in + ((long)(z * CI + ci) << 12) + (y << 6);
    float v0 = 0.f, v1 = 0.f;
    if ((unsigned)y < 64u) {
        if ((unsigned)x < 64u) v0 = row[x];
        if ((unsigned)(x + 1) < 64u) v1 = row[x + 1];
    }
    *(float2*)&out[((long)(z * K + gk) << 12) + n] = make_float2(v0, v1);
}

// ---------------- conv-as-GEMM (round-11 proven, FFMA2 at RF roofline) ----------------
template <int BM, int TM>
__global__ void __launch_bounds__(256, 2)
gemm_conv_kernel(const float* __restrict__ I, int K, const ull* __restrict__ WtD, int CO,
                 const float* __restrict__ bias,
                 float* __restrict__ outA, long sA, float* __restrict__ outB, long sB) {
    extern __shared__ __align__(16) char gsm[];
    const int ABY = 16 * BM * 8;
    uint32_t sbase = smem_u32(gsm);
    int z = blockIdx.z, sel = z >> 2, bb = z & 3;
    float* out = sel ? outB : outA;
    long os = sel ? sB : sA;
    int m0 = blockIdx.y * BM;
    int n0 = blockIdx.x * 128;
    int tid = threadIdx.x, tx = tid & 15, ty = tid >> 4;
    const float* Ib = I + (long)z * K * NPIX;

    ull acc[TM][4];
#pragma unroll
    for (int u = 0; u < TM; u++)
#pragma unroll
        for (int v = 0; v < 4; v++) acc[u][v] = 0ull;

    auto issue = [&](int c, int st) {
        int k0 = c * 16;
        uint32_t da = sbase + (uint32_t)st * ABY;
        uint32_t db = sbase + 3u * ABY + (uint32_t)st * 8192;
        const int NA = BM / 32;
#pragma unroll
        for (int it = 0; it < NA; it++) {
            int e = tid + it * 256;
            int k = e / (BM / 2), c16 = e % (BM / 2);
            const ull* src = WtD + (long)(k0 + k) * CO + m0 + c16 * 2;
            CP_ASYNC16(da + (uint32_t)(k * BM * 8 + c16 * 16), src);
        }
#pragma unroll
        for (int it = 0; it < 2; it++) {
            int e = tid + it * 256;
            int k = e >> 5, c16 = e & 31;
            const float* src = Ib + (long)(k0 + k) * NPIX + n0 + c16 * 4;
            CP_ASYNC16(db + (uint32_t)(k * 512 + c16 * 16), src);
        }
        CP_COMMIT();
    };

    int nch = K / 16;
    issue(0, 0);
    issue(1, 1);

    for (int c = 0; c < nch; c++) {
        int st = c % 3;
        if (c + 1 < nch) CP_WAIT1(); else CP_WAIT0();
        __syncthreads();
        if (c + 2 < nch) issue(c + 2, (c + 2) % 3);
        const ull* AD = (const ull*)(gsm + st * ABY);
        const ull* BsU = (const ull*)(gsm + 3 * ABY + st * 8192);
#pragma unroll
        for (int kk = 0; kk < 16; kk++) {
            ull a2[TM];
#pragma unroll
            for (int h = 0; h < TM / 2; h++) {
                ulonglong2 t = *(const ulonglong2*)&AD[kk * BM + ty * TM + h * 2];
                a2[h * 2] = t.x;
                a2[h * 2 + 1] = t.y;
            }
            ull bq[4];
#pragma unroll
            for (int s = 0; s < 4; s++) bq[s] = BsU[kk * 64 + s * 16 + tx];
#pragma unroll
            for (int u = 0; u < TM; u++)
#pragma unroll
                for (int s = 0; s < 4; s++) ffma2(acc[u][s], a2[u], bq[s]);
        }
    }
#pragma unroll
    for (int u = 0; u < TM; u++) {
        int m = m0 + ty * TM + u;
        float bval = bias[m];
        long base = (long)bb * os + (long)m * NPIX + n0;
#pragma unroll
        for (int s = 0; s < 4; s++) {
            float2 o;
            o.x = lo32(acc[u][s]) + bval;
            o.y = hi32(acc[u][s]) + bval;
            *(float2*)&out[base + s * 32 + tx * 2] = o;
        }
    }
}

// ---------------- split to bf16 h/m/l stacks + key norms ----------------
__global__ void split_kernel(const float* __restrict__ f1out, const float* __restrict__ f2,
                             __nv_bfloat16* __restrict__ QS, __nv_bfloat16* __restrict__ KS,
                             float* __restrict__ b2n) {
    __shared__ __nv_bfloat16 sh[3][64][64];
    __shared__ float snorm[256];
    int n0 = blockIdx.x * 64;
    int src = blockIdx.y;
    int b = blockIdx.z;
    const float* f = src ? (f2 + (long)b * C3 * NPIX) : (f1out + (long)b * 512 * NPIX);
    __nv_bfloat16* dst = (src ? KS : QS) + (long)b * NPIX * 768;
    int tid = threadIdx.x;
    int nl = tid & 63, cq = tid >> 6;
    float nacc = 0.f;
    for (int cc = 0; cc < 4; cc++) {
        int cbase = cc * 64;
#pragma unroll
        for (int r = 0; r < 16; r++) {
            int cl = cq + r * 4;
            float x = f[(long)(cbase + cl) * NPIX + n0 + nl];
            __nv_bfloat16 h = __float2bfloat16(x);
            float rr = x - __bfloat162float(h);
            __nv_bfloat16 m = __float2bfloat16(rr);
            float r2 = rr - __bfloat162float(m);
            sh[0][cl][nl] = h;
            sh[1][cl][nl] = m;
            sh[2][cl][nl] = __float2bfloat16(r2);
            nacc += x * x;
        }
        __syncthreads();
        int nl2 = tid >> 2;
        int cg = (tid & 3) * 16;
#pragma unroll
        for (int s = 0; s < 3; s++) {
            __nv_bfloat16* drow = dst + (long)(n0 + nl2) * 768 + s * 256 + cbase + cg;
#pragma unroll
            for (int j = 0; j < 16; j++) drow[j] = sh[s][cg + j][nl2];
        }
        __syncthreads();
    }
    if (src == 1) {
        snorm[tid] = nacc;
        __syncthreads();
        if (tid < 64)
            b2n[(long)b * NPIX + n0 + tid] =
                snorm[tid] + snorm[tid + 64] + snorm[tid + 128] + snorm[tid + 192];
    }
}

// ---------------- dist GEMM + argmin: superchunk mma.sync (h/m/l loaded once per window) ----------------
// Stage = 32 k-cols x 3 segs of Q (24KB) + same of K (24KB) = 48KB; 2 stages, 2 CTAs/SM.
#define MST 49152
#define MSM_TOTAL (2 * MST)

__global__ void __launch_bounds__(256, 2)
dist_mma_kernel(const __nv_bfloat16* __restrict__ QS, const __nv_bfloat16* __restrict__ KS,
                const float* __restrict__ b2n, float* __restrict__ pval,
                int* __restrict__ pidx) {
    extern __shared__ __align__(16) char dsm[];
    uint32_t sb = smem_u32(dsm);
    int b = blockIdx.z;
    int jq = blockIdx.y;
    int j0 = jq * 128;
    int i0 = blockIdx.x * 128;
    int tid = threadIdx.x;
    int lane = tid & 31, wid = tid >> 5;
    int wm = wid & 1, wn = wid >> 1;

    const __nv_bfloat16* Qb = QS + (long)(b * NPIX + i0) * 768;
    const __nv_bfloat16* Kb = KS + (long)(b * NPIX + j0) * 768;
    const float* bn = b2n + (long)b * NPIX;

    float acc[4][4][4];
#pragma unroll
    for (int mt = 0; mt < 4; mt++)
#pragma unroll
        for (int nt = 0; nt < 4; nt++)
#pragma unroll
            for (int q = 0; q < 4; q++) acc[mt][nt][q] = 0.f;

    // stage holds all 3 segments of a 32-k window: granule g = s*512 + row*4 + (k8 ^ ((row>>1)&3))
    auto issue = [&](int c, int st) {
        uint32_t dq = sb + (uint32_t)st * MST;
        uint32_t dk = dq + 24576;
        int kb = c * 32;
#pragma unroll
        for (int it = 0; it < 6; it++) {
            int e = tid + it * 256;                 // 1536 granules each
            int s = e >> 9;
            int row = (e >> 2) & 127;
            int k8 = e & 3;
            uint32_t g = (uint32_t)((s << 9) + row * 4 + (k8 ^ ((row >> 1) & 3))) << 4;
            const __nv_bfloat16* sq = Qb + (long)row * 768 + s * 256 + kb + k8 * 8;
            const __nv_bfloat16* sk = Kb + (long)row * 768 + s * 256 + kb + k8 * 8;
            CP_ASYNC16(dq + g, sq);
            CP_ASYNC16(dk + g, sk);
        }
        CP_COMMIT();
    };

    const int NCH = 8;
    issue(0, 0);

    for (int c = 0; c < NCH; c++) {
        int st = c & 1;
        if (c + 1 < NCH) CP_WAIT1(); else CP_WAIT0();
        __syncthreads();
        if (c + 1 < NCH) issue(c + 1, 1 - st);
        uint32_t Ab = sb + (uint32_t)st * MST;
        uint32_t Bb = Ab + 24576;
#pragma unroll
        for (int ks = 0; ks < 2; ks++) {
            // B fragments for all 3 segments (reused across sq)
            uint32_t bf[3][4][2];
#pragma unroll
            for (int sk = 0; sk < 3; sk++)
#pragma unroll
                for (int nt = 0; nt < 4; nt++) {
                    int rowb = wn * 32 + nt * 8 + (lane & 7);
                    int k8 = ks * 2 + ((lane >> 3) & 1);
                    uint32_t g = (uint32_t)((sk << 9) + rowb * 4 + (k8 ^ ((rowb >> 1) & 3))) << 4;
                    LDSM_X2(bf[sk][nt][0], bf[sk][nt][1], Bb + g);
                }
#pragma unroll
            for (int sq = 0; sq < 3; sq++) {
                uint32_t af[4][4];
#pragma unroll
                for (int mt = 0; mt < 4; mt++) {
                    int row = wm * 64 + mt * 16 + (lane & 15);
                    int k8 = ks * 2 + (lane >> 4);
                    uint32_t g = (uint32_t)((sq << 9) + row * 4 + (k8 ^ ((row >> 1) & 3))) << 4;
                    LDSM_X4(af[mt][0], af[mt][1], af[mt][2], af[mt][3], Ab + g);
                }
                int nsk = 3 - sq;  // sq=0: hh,hm,hl ; sq=1: mh,mm ; sq=2: lh
#pragma unroll
                for (int sk = 0; sk < 3; sk++) {
                    if (sk >= nsk) break;
#pragma unroll
                    for (int mt = 0; mt < 4; mt++)
#pragma unroll
                        for (int nt = 0; nt < 4; nt++) MMA_BF16(acc[mt][nt], af[mt], bf[sk][nt]);
                }
            }
        }
    }

    // epilogue: dist = bn[j] - 2*cross, running argmin (first-index ties)
    float bnv[4][2];
#pragma unroll
    for (int nt = 0; nt < 4; nt++) {
        int jj = j0 + wn * 32 + nt * 8 + (lane & 3) * 2;
        bnv[nt][0] = __ldg(&bn[jj]);
        bnv[nt][1] = __ldg(&bn[jj + 1]);
    }
    float bvA[4], bvB[4];
    int biA[4], biB[4];
#pragma unroll
    for (int mt = 0; mt < 4; mt++) {
        bvA[mt] = 3.4e38f; biA[mt] = 0;
        bvB[mt] = 3.4e38f; biB[mt] = 0;
#pragma unroll
        for (int nt = 0; nt < 4; nt++)
#pragma unroll
            for (int p = 0; p < 2; p++) {
                int j = j0 + wn * 32 + nt * 8 + (lane & 3) * 2 + p;
                float dA = bnv[nt][p] - 2.f * acc[mt][nt][p];
                if (dA < bvA[mt]) { bvA[mt] = dA; biA[mt] = j; }
                float dB = bnv[nt][p] - 2.f * acc[mt][nt][2 + p];
                if (dB < bvB[mt]) { bvB[mt] = dB; biB[mt] = j; }
            }
#pragma unroll
        for (int m = 1; m <= 2; m <<= 1) {
            float ov = __shfl_xor_sync(0xffffffffu, bvA[mt], m);
            int oi = __shfl_xor_sync(0xffffffffu, biA[mt], m);
            if (ov < bvA[mt] || (ov == bvA[mt] && oi < biA[mt])) { bvA[mt] = ov; biA[mt] = oi; }
            ov = __shfl_xor_sync(0xffffffffu, bvB[mt], m);
            oi = __shfl_xor_sync(0xffffffffu, biB[mt], m);
            if (ov < bvB[mt] || (ov == bvB[mt] && oi < biB[mt])) { bvB[mt] = ov; biB[mt] = oi; }
        }
    }
    __syncthreads();
    float* rv = (float*)dsm;
    int* ri = (int*)(dsm + 2048);
    if ((lane & 3) == 0) {
#pragma unroll
        for (int mt = 0; mt < 4; mt++) {
            int r = wm * 64 + mt * 16 + (lane >> 2);
            rv[wn * 128 + r] = bvA[mt];
            ri[wn * 128 + r] = biA[mt];
            rv[wn * 128 + r + 8] = bvB[mt];
            ri[wn * 128 + r + 8] = biB[mt];
        }
    }
    __syncthreads();
    if (tid < 128) {
        float bv = rv[tid];
        int bi = ri[tid];
#pragma unroll
        for (int w = 1; w < 4; w++) {
            float v = rv[w * 128 + tid];
            int ii = ri[w * 128 + tid];
            if (v < bv || (v == bv && ii < bi)) { bv = v; bi = ii; }
        }
        long o = ((long)(jq * NB + b) << 12) + i0 + tid;
        pval[o] = bv;
        pidx[o] = bi;
    }
}

// ---------------- merge 32 j-tile candidates ----------------
__global__ void merge_kernel(const float* __restrict__ pval, const int* __restrict__ pidx,
                             int* __restrict__ idxout) {
    int t = blockIdx.x * blockDim.x + threadIdx.x;
    if (t >= NB * NPIX) return;
    int b = t >> 12, i = t & (NPIX - 1);
    float bv = 3.4e38f;
    int bi = 0;
#pragma unroll 4
    for (int jq = 0; jq < 32; jq++) {
        long o = ((long)(jq * NB + b) << 12) + i;
        float v = pval[o];
        int ii = pidx[o];
        if (v < bv || (v == bv && ii < bi)) { bv = v; bi = ii; }
    }
    idxout[t] = bi;
}

// ---------------- gather ----------------
__global__ void gather_kernel(const float* __restrict__ f2, const int* __restrict__ idx,
                              float* __restrict__ out) {
    long t = (long)blockIdx.x * blockDim.x + threadIdx.x;
    if (t >= (long)NB * C3 * NPIX) return;
    int j = (int)(t & (NPIX - 1));
    int c = (int)((t >> 12) & 255);
    int b = (int)(t >> 20);
    int id = idx[(long)b * NPIX + j];
    out[((long)b * 512 + 256 + c) * NPIX + j] = f2[((long)b * C3 + c) * NPIX + id];
}

// ---------------- launch ----------------
extern "C" void kernel_launch(void* const* d_in, const int* in_sizes, int n_in,
                              void* d_out, int out_size) {
    const float* x1 = (const float*)d_in[0];
    const float* x2 = (const float*)d_in[1];
    const float* w1 = (const float*)d_in[2];
    const float* b1 = (const float*)d_in[3];
    const float* w2 = (const float*)d_in[4];
    const float* b2 = (const float*)d_in[5];
    const float* w3 = (const float*)d_in[6];
    const float* b3 = (const float*)d_in[7];
    float* out = (float*)d_out;

    float *T1, *T2, *IC, *F2, *B2N, *PVAL;
    int *IDX, *PIDX;
    ull *Wt2D, *Wt3D;
    __nv_bfloat16 *QS, *KS;
    cudaGetSymbolAddress((void**)&T1, g_T1);
    cudaGetSymbolAddress((void**)&T2, g_T2);
    cudaGetSymbolAddress((void**)&IC, g_IC);
    cudaGetSymbolAddress((void**)&F2, g_F2);
    cudaGetSymbolAddress((void**)&B2N, g_B2N);
    cudaGetSymbolAddress((void**)&IDX, g_IDX);
    cudaGetSymbolAddress((void**)&Wt2D, g_Wt2D);
    cudaGetSymbolAddress((void**)&Wt3D, g_Wt3D);
    cudaGetSymbolAddress((void**)&PVAL, g_PVAL);
    cudaGetSymbolAddress((void**)&PIDX, g_PIDX);
    cudaGetSymbolAddress((void**)&QS, g_QS);
    cudaGetSymbolAddress((void**)&KS, g_KS);

    cudaFuncSetAttribute(dist_mma_kernel, cudaFuncAttributeMaxDynamicSharedMemorySize,
                         MSM_TOTAL);
    cudaFuncSetAttribute(gemm_conv_kernel<64, 4>, cudaFuncAttributeMaxDynamicSharedMemorySize,
                         3 * (16 * 64 * 8) + 3 * 8192);
    cudaFuncSetAttribute(gemm_conv_kernel<128, 8>, cudaFuncAttributeMaxDynamicSharedMemorySize,
                         3 * (16 * 128 * 8) + 3 * 8192);

    prep_kernel<<<(C2 * 288 + C3 * 576 + 255) / 256, 256>>>(w2, w3, Wt2D, Wt3D);
    conv1_kernel<<<dim3(NPIX / 256, 8), 256>>>(x1, x2, w1, b1, T1);
    im2col_kernel<<<dim3(288, 8, 8), 256>>>(T1, C1, IC);
    gemm_conv_kernel<64, 4><<<dim3(32, 1, 8), 256, 3 * (16 * 64 * 8) + 3 * 8192>>>(
        IC, 288, Wt2D, C2, b2, T2, (long)C2 * NPIX, T2 + (long)NB * C2 * NPIX, (long)C2 * NPIX);
    im2col_kernel<<<dim3(576, 8, 8), 256>>>(T2, C2, IC);
    gemm_conv_kernel<128, 8><<<dim3(32, 2, 8), 256, 3 * (16 * 128 * 8) + 3 * 8192>>>(
        IC, 576, Wt3D, C3, b3, out, (long)512 * NPIX, F2, (long)C3 * NPIX);
    split_kernel<<<dim3(NPIX / 64, 2, NB), 256>>>(out, F2, QS, KS, B2N);
    dist_mma_kernel<<<dim3(32, 32, NB), 256, MSM_TOTAL>>>(QS, KS, B2N, PVAL, PIDX);
    merge_kernel<<<(NB * NPIX + 255) / 256, 256>>>(PVAL, PIDX, IDX);
    gather_kernel<<<(int)(((long)NB * C3 * NPIX + 255) / 256), 256>>>(F2, IDX, out);
}

// round 14
// speedup vs baseline: 4.1579x; 1.3731x over previous
#include <cuda_runtime.h>
#include <cuda_fp16.h>
#include <cstdint>

#define HH 64
#define WW 64
#define NPIX 4096
#define NB 4
#define C1 32
#define C2 64
#define C3 256

typedef unsigned long long ull;

__device__ __forceinline__ ull dup2(float v) {
    ull r;
    asm("mov.b64 %0, {%1, %1};" : "=l"(r) : "r"(__float_as_uint(v)));
    return r;
}
__device__ __forceinline__ void ffma2(ull& acc, ull a, ull b) {
    asm("fma.rn.f32x2 %0, %1, %2, %0;" : "+l"(acc) : "l"(a), "l"(b));
}
__device__ __forceinline__ float lo32(ull x) { return __uint_as_float((unsigned int)x); }
__device__ __forceinline__ float hi32(ull x) { return __uint_as_float((unsigned int)(x >> 32)); }
__device__ __forceinline__ uint32_t smem_u32(const void* p) {
    uint32_t a;
    asm("{ .reg .u64 t; cvta.to.shared.u64 t, %1; cvt.u32.u64 %0, t; }" : "=r"(a) : "l"(p));
    return a;
}
#define CP_ASYNC16(dst, src) \
    asm volatile("cp.async.cg.shared.global [%0], [%1], 16;" :: "r"(dst), "l"(src) : "memory")
#define CP_COMMIT() asm volatile("cp.async.commit_group;" ::: "memory")
#define CP_WAIT1() asm volatile("cp.async.wait_group 1;" ::: "memory")
#define CP_WAIT0() asm volatile("cp.async.wait_group 0;" ::: "memory")
#define LDSM_X4(r0, r1, r2, r3, a) \
    asm volatile("ldmatrix.sync.aligned.m8n8.x4.shared.b16 {%0,%1,%2,%3}, [%4];" \
        : "=r"(r0), "=r"(r1), "=r"(r2), "=r"(r3) : "r"(a))
#define LDSM_X2(r0, r1, a) \
    asm volatile("ldmatrix.sync.aligned.m8n8.x2.shared.b16 {%0,%1}, [%2];" \
        : "=r"(r0), "=r"(r1) : "r"(a))
#define MMA_F16(d, a, bf) \
    asm volatile( \
        "mma.sync.aligned.m16n8k16.row.col.f32.f16.f16.f32 " \
        "{%0,%1,%2,%3}, {%4,%5,%6,%7}, {%8,%9}, {%0,%1,%2,%3};" \
        : "+f"((d)[0]), "+f"((d)[1]), "+f"((d)[2]), "+f"((d)[3]) \
        : "r"((a)[0]), "r"((a)[1]), "r"((a)[2]), "r"((a)[3]), "r"((bf)[0]), "r"((bf)[1]))

// ---------------- static device scratch ----------------
__device__ float g_T1[2 * NB * C1 * NPIX];
__device__ float g_T2[2 * NB * C2 * NPIX];
__device__ __align__(16) float g_IC[2 * NB * 576 * NPIX];
__device__ float g_F2[NB * C3 * NPIX];
__device__ float g_B2N[NB * NPIX];
__device__ int g_IDX[NB * NPIX];
__device__ __align__(16) ull g_Wt2D[288 * C2];
__device__ __align__(16) ull g_Wt3D[576 * C3];
__device__ float g_PVAL[32 * NB * NPIX];
__device__ int g_PIDX[32 * NB * NPIX];
__device__ __align__(16) __half g_QS[(long)NB * NPIX * 512];
__device__ __align__(16) __half g_KS[(long)NB * NPIX * 512];

// ---------------- prep: transpose + duplicate weights ----------------
__global__ void prep_kernel(const float* __restrict__ w2, const float* __restrict__ w3,
                            ull* __restrict__ Wt2D, ull* __restrict__ Wt3D) {
    int t = blockIdx.x * blockDim.x + threadIdx.x;
    if (t < C2 * 288) {
        int co = t / 288, k = t - co * 288;
        Wt2D[k * C2 + co] = dup2(w2[t]);
    } else {
        int u = t - C2 * 288;
        if (u < C3 * 576) {
            int co = u / 576, k = u - co * 576;
            Wt3D[k * C3 + co] = dup2(w3[u]);
        }
    }
}

// ---------------- conv1 ----------------
__global__ void conv1_kernel(const float* __restrict__ x1, const float* __restrict__ x2,
                             const float* __restrict__ w, const float* __restrict__ bias,
                             float* __restrict__ out) {
    int p = blockIdx.x * blockDim.x + threadIdx.x;
    int z = blockIdx.y;
    if (p >= NPIX) return;
    const float* x = (z >> 2) ? x2 : x1;
    int b = z & 3;
    int y = p >> 6, xx = p & 63;
    const float* xb = x + (long)b * NPIX;
    float in[9];
#pragma unroll
    for (int ky = 0; ky < 3; ky++)
#pragma unroll
        for (int kx = 0; kx < 3; kx++) {
            int yy = y + ky - 1, xc = xx + kx - 1;
            in[ky * 3 + kx] =
                ((unsigned)yy < (unsigned)HH && (unsigned)xc < (unsigned)WW) ? xb[yy * WW + xc] : 0.f;
        }
#pragma unroll 4
    for (int co = 0; co < C1; co++) {
        float acc = bias[co];
#pragma unroll
        for (int t = 0; t < 9; t++) acc += w[co * 9 + t] * in[t];
        out[((long)z * C1 + co) * NPIX + p] = acc;
    }
}

// ---------------- im2col ----------------
__global__ void im2col_kernel(const float* __restrict__ in, int CI, float* __restrict__ out) {
    int gk = blockIdx.x;
    int z = blockIdx.y;
    int n = ((blockIdx.z << 8) + threadIdx.x) << 1;
    int K = CI * 9;
    int ci = gk / 9;
    int tap = gk - ci * 9;
    int ky = tap / 3 - 1, kx = tap - (tap / 3) * 3 - 1;
    int y = (n >> 6) + ky;
    int x = (n & 63) + kx;
    const float* row = in + ((long)(z * CI + ci) << 12) + (y << 6);
    float v0 = 0.f, v1 = 0.f;
    if ((unsigned)y < 64u) {
        if ((unsigned)x < 64u) v0 = row[x];
        if ((unsigned)(x + 1) < 64u) v1 = row[x + 1];
    }
    *(float2*)&out[((long)(z * K + gk) << 12) + n] = make_float2(v0, v1);
}

// ---------------- conv-as-GEMM (round-11 proven, FFMA2 at RF roofline) ----------------
template <int BM, int TM>
__global__ void __launch_bounds__(256, 2)
gemm_conv_kernel(const float* __restrict__ I, int K, const ull* __restrict__ WtD, int CO,
                 const float* __restrict__ bias,
                 float* __restrict__ outA, long sA, float* __restrict__ outB, long sB) {
    extern __shared__ __align__(16) char gsm[];
    const int ABY = 16 * BM * 8;
    uint32_t sbase = smem_u32(gsm);
    int z = blockIdx.z, sel = z >> 2, bb = z & 3;
    float* out = sel ? outB : outA;
    long os = sel ? sB : sA;
    int m0 = blockIdx.y * BM;
    int n0 = blockIdx.x * 128;
    int tid = threadIdx.x, tx = tid & 15, ty = tid >> 4;
    const float* Ib = I + (long)z * K * NPIX;

    ull acc[TM][4];
#pragma unroll
    for (int u = 0; u < TM; u++)
#pragma unroll
        for (int v = 0; v < 4; v++) acc[u][v] = 0ull;

    auto issue = [&](int c, int st) {
        int k0 = c * 16;
        uint32_t da = sbase + (uint32_t)st * ABY;
        uint32_t db = sbase + 3u * ABY + (uint32_t)st * 8192;
        const int NA = BM / 32;
#pragma unroll
        for (int it = 0; it < NA; it++) {
            int e = tid + it * 256;
            int k = e / (BM / 2), c16 = e % (BM / 2);
            const ull* src = WtD + (long)(k0 + k) * CO + m0 + c16 * 2;
            CP_ASYNC16(da + (uint32_t)(k * BM * 8 + c16 * 16), src);
        }
#pragma unroll
        for (int it = 0; it < 2; it++) {
            int e = tid + it * 256;
            int k = e >> 5, c16 = e & 31;
            const float* src = Ib + (long)(k0 + k) * NPIX + n0 + c16 * 4;
            CP_ASYNC16(db + (uint32_t)(k * 512 + c16 * 16), src);
        }
        CP_COMMIT();
    };

    int nch = K / 16;
    issue(0, 0);
    issue(1, 1);

    for (int c = 0; c < nch; c++) {
        int st = c % 3;
        if (c + 1 < nch) CP_WAIT1(); else CP_WAIT0();
        __syncthreads();
        if (c + 2 < nch) issue(c + 2, (c + 2) % 3);
        const ull* AD = (const ull*)(gsm + st * ABY);
        const ull* BsU = (const ull*)(gsm + 3 * ABY + st * 8192);
#pragma unroll
        for (int kk = 0; kk < 16; kk++) {
            ull a2[TM];
#pragma unroll
            for (int h = 0; h < TM / 2; h++) {
                ulonglong2 t = *(const ulonglong2*)&AD[kk * BM + ty * TM + h * 2];
                a2[h * 2] = t.x;
                a2[h * 2 + 1] = t.y;
            }
            ull bq[4];
#pragma unroll
            for (int s = 0; s < 4; s++) bq[s] = BsU[kk * 64 + s * 16 + tx];
#pragma unroll
            for (int u = 0; u < TM; u++)
#pragma unroll
                for (int s = 0; s < 4; s++) ffma2(acc[u][s], a2[u], bq[s]);
        }
    }
#pragma unroll
    for (int u = 0; u < TM; u++) {
        int m = m0 + ty * TM + u;
        float bval = bias[m];
        long base = (long)bb * os + (long)m * NPIX + n0;
#pragma unroll
        for (int s = 0; s < 4; s++) {
            float2 o;
            o.x = lo32(acc[u][s]) + bval;
            o.y = hi32(acc[u][s]) + bval;
            *(float2*)&out[base + s * 32 + tx * 2] = o;
        }
    }
}

// ---------------- split to fp16 h/m stacks (512 k each) + key norms ----------------
__global__ void split_kernel(const float* __restrict__ f1out, const float* __restrict__ f2,
                             __half* __restrict__ QS, __half* __restrict__ KS,
                             float* __restrict__ b2n) {
    __shared__ __half sh[2][64][64];
    __shared__ float snorm[256];
    int n0 = blockIdx.x * 64;
    int src = blockIdx.y;
    int b = blockIdx.z;
    const float* f = src ? (f2 + (long)b * C3 * NPIX) : (f1out + (long)b * 512 * NPIX);
    __half* dst = (src ? KS : QS) + (long)b * NPIX * 512;
    int tid = threadIdx.x;
    int nl = tid & 63, cq = tid >> 6;
    float nacc = 0.f;
    for (int cc = 0; cc < 4; cc++) {
        int cbase = cc * 64;
#pragma unroll
        for (int r = 0; r < 16; r++) {
            int cl = cq + r * 4;
            float x = f[(long)(cbase + cl) * NPIX + n0 + nl];
            __half h = __float2half_rn(x);
            float rr = x - __half2float(h);
            sh[0][cl][nl] = h;
            sh[1][cl][nl] = __float2half_rn(rr);
            nacc += x * x;
        }
        __syncthreads();
        int nl2 = tid >> 2;
        int cg = (tid & 3) * 16;
#pragma unroll
        for (int s = 0; s < 2; s++) {
            __half* drow = dst + (long)(n0 + nl2) * 512 + s * 256 + cbase + cg;
#pragma unroll
            for (int j = 0; j < 16; j++) drow[j] = sh[s][cg + j][nl2];
        }
        __syncthreads();
    }
    if (src == 1) {
        snorm[tid] = nacc;
        __syncthreads();
        if (tid < 64)
            b2n[(long)b * NPIX + n0 + tid] =
                snorm[tid] + snorm[tid + 64] + snorm[tid + 128] + snorm[tid + 192];
    }
}

// ---------------- dist GEMM + argmin: fp16 2-segment, 3 products, mma.sync ----------------
// Stage = 32 k-cols x 2 segs of Q (16KB) + K (16KB) = 32KB; 3 stages, 2 CTAs/SM.
#define MST 32768
#define MSM_TOTAL (3 * MST)

__global__ void __launch_bounds__(256, 2)
dist_mma_kernel(const __half* __restrict__ QS, const __half* __restrict__ KS,
                const float* __restrict__ b2n, float* __restrict__ pval,
                int* __restrict__ pidx) {
    extern __shared__ __align__(16) char dsm[];
    uint32_t sb = smem_u32(dsm);
    int b = blockIdx.z;
    int jq = blockIdx.y;
    int j0 = jq * 128;
    int i0 = blockIdx.x * 128;
    int tid = threadIdx.x;
    int lane = tid & 31, wid = tid >> 5;
    int wm = wid & 1, wn = wid >> 1;

    const __half* Qb = QS + (long)(b * NPIX + i0) * 512;
    const __half* Kb = KS + (long)(b * NPIX + j0) * 512;
    const float* bn = b2n + (long)b * NPIX;

    float acc[4][4][4];
#pragma unroll
    for (int mt = 0; mt < 4; mt++)
#pragma unroll
        for (int nt = 0; nt < 4; nt++)
#pragma unroll
            for (int q = 0; q < 4; q++) acc[mt][nt][q] = 0.f;

    // stage granule: g = s*512 + row*4 + (k8 ^ ((row>>1)&3)), s<2, k8<4
    auto issue = [&](int c, int st) {
        uint32_t dq = sb + (uint32_t)st * MST;
        uint32_t dk = dq + 16384;
        int kb = c * 32;
#pragma unroll
        for (int it = 0; it < 4; it++) {
            int e = tid + it * 256;                 // 1024 granules each
            int s = e >> 9;
            int row = (e >> 2) & 127;
            int k8 = e & 3;
            uint32_t g = (uint32_t)((s << 9) + row * 4 + (k8 ^ ((row >> 1) & 3))) << 4;
            const __half* sq = Qb + (long)row * 512 + s * 256 + kb + k8 * 8;
            const __half* sk = Kb + (long)row * 512 + s * 256 + kb + k8 * 8;
            CP_ASYNC16(dq + g, sq);
            CP_ASYNC16(dk + g, sk);
        }
        CP_COMMIT();
    };

    const int NCH = 8;
    issue(0, 0);
    issue(1, 1);

    for (int c = 0; c < NCH; c++) {
        int st = c % 3;
        if (c + 1 < NCH) CP_WAIT1(); else CP_WAIT0();
        __syncthreads();
        if (c + 2 < NCH) issue(c + 2, (c + 2) % 3);
        uint32_t Ab = sb + (uint32_t)st * MST;
        uint32_t Bb = Ab + 16384;
#pragma unroll
        for (int ks = 0; ks < 2; ks++) {
            // B fragments for both segments (reused across sq)
            uint32_t bf[2][4][2];
#pragma unroll
            for (int sk = 0; sk < 2; sk++)
#pragma unroll
                for (int nt = 0; nt < 4; nt++) {
                    int rowb = wn * 32 + nt * 8 + (lane & 7);
                    int k8 = ks * 2 + ((lane >> 3) & 1);
                    uint32_t g = (uint32_t)((sk << 9) + rowb * 4 + (k8 ^ ((rowb >> 1) & 3))) << 4;
                    LDSM_X2(bf[sk][nt][0], bf[sk][nt][1], Bb + g);
                }
#pragma unroll
            for (int sq = 0; sq < 2; sq++) {
                uint32_t af[4][4];
#pragma unroll
                for (int mt = 0; mt < 4; mt++) {
                    int row = wm * 64 + mt * 16 + (lane & 15);
                    int k8 = ks * 2 + (lane >> 4);
                    uint32_t g = (uint32_t)((sq << 9) + row * 4 + (k8 ^ ((row >> 1) & 3))) << 4;
                    LDSM_X4(af[mt][0], af[mt][1], af[mt][2], af[mt][3], Ab + g);
                }
                int nsk = 2 - sq;  // sq=0: hh,hm ; sq=1: mh
#pragma unroll
                for (int sk = 0; sk < 2; sk++) {
                    if (sk >= nsk) break;
#pragma unroll
                    for (int mt = 0; mt < 4; mt++)
#pragma unroll
                        for (int nt = 0; nt < 4; nt++) MMA_F16(acc[mt][nt], af[mt], bf[sk][nt]);
                }
            }
        }
    }

    // epilogue: dist = bn[j] - 2*cross, running argmin (first-index ties)
    float bnv[4][2];
#pragma unroll
    for (int nt = 0; nt < 4; nt++) {
        int jj = j0 + wn * 32 + nt * 8 + (lane & 3) * 2;
        bnv[nt][0] = __ldg(&bn[jj]);
        bnv[nt][1] = __ldg(&bn[jj + 1]);
    }
    float bvA[4], bvB[4];
    int biA[4], biB[4];
#pragma unroll
    for (int mt = 0; mt < 4; mt++) {
        bvA[mt] = 3.4e38f; biA[mt] = 0;
        bvB[mt] = 3.4e38f; biB[mt] = 0;
#pragma unroll
        for (int nt = 0; nt < 4; nt++)
#pragma unroll
            for (int p = 0; p < 2; p++) {
                int j = j0 + wn * 32 + nt * 8 + (lane & 3) * 2 + p;
                float dA = bnv[nt][p] - 2.f * acc[mt][nt][p];
                if (dA < bvA[mt]) { bvA[mt] = dA; biA[mt] = j; }
                float dB = bnv[nt][p] - 2.f * acc[mt][nt][2 + p];
                if (dB < bvB[mt]) { bvB[mt] = dB; biB[mt] = j; }
            }
#pragma unroll
        for (int m = 1; m <= 2; m <<= 1) {
            float ov = __shfl_xor_sync(0xffffffffu, bvA[mt], m);
            int oi = __shfl_xor_sync(0xffffffffu, biA[mt], m);
            if (ov < bvA[mt] || (ov == bvA[mt] && oi < biA[mt])) { bvA[mt] = ov; biA[mt] = oi; }
            ov = __shfl_xor_sync(0xffffffffu, bvB[mt], m);
            oi = __shfl_xor_sync(0xffffffffu, biB[mt], m);
            if (ov < bvB[mt] || (ov == bvB[mt] && oi < biB[mt])) { bvB[mt] = ov; biB[mt] = oi; }
        }
    }
    __syncthreads();
    float* rv = (float*)dsm;
    int* ri = (int*)(dsm + 2048);
    if ((lane & 3) == 0) {
#pragma unroll
        for (int mt = 0; mt < 4; mt++) {
            int r = wm * 64 + mt * 16 + (lane >> 2);
            rv[wn * 128 + r] = bvA[mt];
            ri[wn * 128 + r] = biA[mt];
            rv[wn * 128 + r + 8] = bvB[mt];
            ri[wn * 128 + r + 8] = biB[mt];
        }
    }
    __syncthreads();
    if (tid < 128) {
        float bv = rv[tid];
        int bi = ri[tid];
#pragma unroll
        for (int w = 1; w < 4; w++) {
            float v = rv[w * 128 + tid];
            int ii = ri[w * 128 + tid];
            if (v < bv || (v == bv && ii < bi)) { bv = v; bi = ii; }
        }
        long o = ((long)(jq * NB + b) << 12) + i0 + tid;
        pval[o] = bv;
        pidx[o] = bi;
    }
}

// ---------------- merge 32 j-tile candidates ----------------
__global__ void merge_kernel(const float* __restrict__ pval, const int* __restrict__ pidx,
                             int* __restrict__ idxout) {
    int t = blockIdx.x * blockDim.x + threadIdx.x;
    if (t >= NB * NPIX) return;
    int b = t >> 12, i = t & (NPIX - 1);
    float bv = 3.4e38f;
    int bi = 0;
#pragma unroll 4
    for (int jq = 0; jq < 32; jq++) {
        long o = ((long)(jq * NB + b) << 12) + i;
        float v = pval[o];
        int ii = pidx[o];
        if (v < bv || (v == bv && ii < bi)) { bv = v; bi = ii; }
    }
    idxout[t] = bi;
}

// ---------------- gather ----------------
__global__ void gather_kernel(const float* __restrict__ f2, const int* __restrict__ idx,
                              float* __restrict__ out) {
    long t = (long)blockIdx.x * blockDim.x + threadIdx.x;
    if (t >= (long)NB * C3 * NPIX) return;
    int j = (int)(t & (NPIX - 1));
    int c = (int)((t >> 12) & 255);
    int b = (int)(t >> 20);
    int id = idx[(long)b * NPIX + j];
    out[((long)b * 512 + 256 + c) * NPIX + j] = f2[((long)b * C3 + c) * NPIX + id];
}

// ---------------- launch ----------------
extern "C" void kernel_launch(void* const* d_in, const int* in_sizes, int n_in,
                              void* d_out, int out_size) {
    const float* x1 = (const float*)d_in[0];
    const float* x2 = (const float*)d_in[1];
    const float* w1 = (const float*)d_in[2];
    const float* b1 = (const float*)d_in[3];
    const float* w2 = (const float*)d_in[4];
    const float* b2 = (const float*)d_in[5];
    const float* w3 = (const float*)d_in[6];
    const float* b3 = (const float*)d_in[7];
    float* out = (float*)d_out;

    float *T1, *T2, *IC, *F2, *B2N, *PVAL;
    int *IDX, *PIDX;
    ull *Wt2D, *Wt3D;
    __half *QS, *KS;
    cudaGetSymbolAddress((void**)&T1, g_T1);
    cudaGetSymbolAddress((void**)&T2, g_T2);
    cudaGetSymbolAddress((void**)&IC, g_IC);
    cudaGetSymbolAddress((void**)&F2, g_F2);
    cudaGetSymbolAddress((void**)&B2N, g_B2N);
    cudaGetSymbolAddress((void**)&IDX, g_IDX);
    cudaGetSymbolAddress((void**)&Wt2D, g_Wt2D);
    cudaGetSymbolAddress((void**)&Wt3D, g_Wt3D);
    cudaGetSymbolAddress((void**)&PVAL, g_PVAL);
    cudaGetSymbolAddress((void**)&PIDX, g_PIDX);
    cudaGetSymbolAddress((void**)&QS, g_QS);
    cudaGetSymbolAddress((void**)&KS, g_KS);

    cudaFuncSetAttribute(dist_mma_kernel, cudaFuncAttributeMaxDynamicSharedMemorySize,
                         MSM_TOTAL);
    cudaFuncSetAttribute(gemm_conv_kernel<64, 4>, cudaFuncAttributeMaxDynamicSharedMemorySize,
                         3 * (16 * 64 * 8) + 3 * 8192);
    cudaFuncSetAttribute(gemm_conv_kernel<128, 8>, cudaFuncAttributeMaxDynamicSharedMemorySize,
                         3 * (16 * 128 * 8) + 3 * 8192);

    prep_kernel<<<(C2 * 288 + C3 * 576 + 255) / 256, 256>>>(w2, w3, Wt2D, Wt3D);
    conv1_kernel<<<dim3(NPIX / 256, 8), 256>>>(x1, x2, w1, b1, T1);
    im2col_kernel<<<dim3(288, 8, 8), 256>>>(T1, C1, IC);
    gemm_conv_kernel<64, 4><<<dim3(32, 1, 8), 256, 3 * (16 * 64 * 8) + 3 * 8192>>>(
        IC, 288, Wt2D, C2, b2, T2, (long)C2 * NPIX, T2 + (long)NB * C2 * NPIX, (long)C2 * NPIX);
    im2col_kernel<<<dim3(576, 8, 8), 256>>>(T2, C2, IC);
    gemm_conv_kernel<128, 8><<<dim3(32, 2, 8), 256, 3 * (16 * 128 * 8) + 3 * 8192>>>(
        IC, 576, Wt3D, C3, b3, out, (long)512 * NPIX, F2, (long)C3 * NPIX);
    split_kernel<<<dim3(NPIX / 64, 2, NB), 256>>>(out, F2, QS, KS, B2N);
    dist_mma_kernel<<<dim3(32, 32, NB), 256, MSM_TOTAL>>>(QS, KS, B2N, PVAL, PIDX);
    merge_kernel<<<(NB * NPIX + 255) / 256, 256>>>(PVAL, PIDX, IDX);
    gather_kernel<<<(int)(((long)NB * C3 * NPIX + 255) / 256), 256>>>(F2, IDX, out);
}

// round 15
// speedup vs baseline: 5.5432x; 1.3332x over previous
#include <cuda_runtime.h>
#include <cuda_fp16.h>
#include <cstdint>

#define HH 64
#define WW 64
#define NPIX 4096
#define NB 4
#define C1 32
#define C2 64
#define C3 256

typedef unsigned long long ull;

__device__ __forceinline__ uint32_t smem_u32(const void* p) {
    uint32_t a;
    asm("{ .reg .u64 t; cvta.to.shared.u64 t, %1; cvt.u32.u64 %0, t; }" : "=r"(a) : "l"(p));
    return a;
}
#define CP_ASYNC16(dst, src) \
    asm volatile("cp.async.cg.shared.global [%0], [%1], 16;" :: "r"(dst), "l"(src) : "memory")
#define CP_COMMIT() asm volatile("cp.async.commit_group;" ::: "memory")
#define CP_WAIT1() asm volatile("cp.async.wait_group 1;" ::: "memory")
#define CP_WAIT0() asm volatile("cp.async.wait_group 0;" ::: "memory")
#define LDSM_X4(r0, r1, r2, r3, a) \
    asm volatile("ldmatrix.sync.aligned.m8n8.x4.shared.b16 {%0,%1,%2,%3}, [%4];" \
        : "=r"(r0), "=r"(r1), "=r"(r2), "=r"(r3) : "r"(a))
#define LDSM_X2(r0, r1, a) \
    asm volatile("ldmatrix.sync.aligned.m8n8.x2.shared.b16 {%0,%1}, [%2];" \
        : "=r"(r0), "=r"(r1) : "r"(a))
#define LDSM_X2T(r0, r1, a) \
    asm volatile("ldmatrix.sync.aligned.m8n8.x2.trans.shared.b16 {%0,%1}, [%2];" \
        : "=r"(r0), "=r"(r1) : "r"(a))
#define MMA_F16(d, a, bf) \
    asm volatile( \
        "mma.sync.aligned.m16n8k16.row.col.f32.f16.f16.f32 " \
        "{%0,%1,%2,%3}, {%4,%5,%6,%7}, {%8,%9}, {%0,%1,%2,%3};" \
        : "+f"((d)[0]), "+f"((d)[1]), "+f"((d)[2]), "+f"((d)[3]) \
        : "r"((a)[0]), "r"((a)[1]), "r"((a)[2]), "r"((a)[3]), "r"((bf)[0]), "r"((bf)[1]))

// ---------------- static device scratch ----------------
__device__ float g_T1[2 * NB * C1 * NPIX];
__device__ float g_T2[2 * NB * C2 * NPIX];
__device__ __align__(16) __half g_ICh[(long)2 * NB * 576 * NPIX];
__device__ __align__(16) __half g_ICm[(long)2 * NB * 576 * NPIX];
__device__ float g_F2[NB * C3 * NPIX];
__device__ float g_B2N[NB * NPIX];
__device__ int g_IDX[NB * NPIX];
__device__ __align__(16) __half g_Wh2[C2 * 288];
__device__ __align__(16) __half g_Wm2[C2 * 288];
__device__ __align__(16) __half g_Wh3[C3 * 576];
__device__ __align__(16) __half g_Wm3[C3 * 576];
__device__ float g_PVAL[32 * NB * NPIX];
__device__ int g_PIDX[32 * NB * NPIX];
__device__ __align__(16) __half g_QS[(long)NB * NPIX * 512];
__device__ __align__(16) __half g_KS[(long)NB * NPIX * 512];

// ---------------- prep: split weights to fp16 h/m (kept [co][k] row-major) ----------------
__global__ void prep_kernel(const float* __restrict__ w2, const float* __restrict__ w3,
                            __half* __restrict__ Wh2, __half* __restrict__ Wm2,
                            __half* __restrict__ Wh3, __half* __restrict__ Wm3) {
    int t = blockIdx.x * blockDim.x + threadIdx.x;
    if (t < C2 * 288) {
        float x = w2[t];
        __half h = __float2half_rn(x);
        Wh2[t] = h;
        Wm2[t] = __float2half_rn(x - __half2float(h));
    } else {
        int u = t - C2 * 288;
        if (u < C3 * 576) {
            float x = w3[u];
            __half h = __float2half_rn(x);
            Wh3[u] = h;
            Wm3[u] = __float2half_rn(x - __half2float(h));
        }
    }
}

// ---------------- conv1 (fp32 direct) ----------------
__global__ void conv1_kernel(const float* __restrict__ x1, const float* __restrict__ x2,
                             const float* __restrict__ w, const float* __restrict__ bias,
                             float* __restrict__ out) {
    int p = blockIdx.x * blockDim.x + threadIdx.x;
    int z = blockIdx.y;
    if (p >= NPIX) return;
    const float* x = (z >> 2) ? x2 : x1;
    int b = z & 3;
    int y = p >> 6, xx = p & 63;
    const float* xb = x + (long)b * NPIX;
    float in[9];
#pragma unroll
    for (int ky = 0; ky < 3; ky++)
#pragma unroll
        for (int kx = 0; kx < 3; kx++) {
            int yy = y + ky - 1, xc = xx + kx - 1;
            in[ky * 3 + kx] =
                ((unsigned)yy < (unsigned)HH && (unsigned)xc < (unsigned)WW) ? xb[yy * WW + xc] : 0.f;
        }
#pragma unroll 4
    for (int co = 0; co < C1; co++) {
        float acc = bias[co];
#pragma unroll
        for (int t = 0; t < 9; t++) acc += w[co * 9 + t] * in[t];
        out[((long)z * C1 + co) * NPIX + p] = acc;
    }
}

// ---------------- im2col with fp16 h/m split: out [z][K][NPIX] ----------------
__global__ void im2col_kernel(const float* __restrict__ in, int CI,
                              __half* __restrict__ oh, __half* __restrict__ om) {
    int gk = blockIdx.x;
    int z = blockIdx.y;
    int n = ((blockIdx.z << 8) + threadIdx.x) << 1;
    int K = CI * 9;
    int ci = gk / 9;
    int tap = gk - ci * 9;
    int ky = tap / 3 - 1, kx = tap - (tap / 3) * 3 - 1;
    int y = (n >> 6) + ky;
    int x = (n & 63) + kx;
    const float* row = in + ((long)(z * CI + ci) << 12) + (y << 6);
    float v0 = 0.f, v1 = 0.f;
    if ((unsigned)y < 64u) {
        if ((unsigned)x < 64u) v0 = row[x];
        if ((unsigned)(x + 1) < 64u) v1 = row[x + 1];
    }
    __half h0 = __float2half_rn(v0), h1 = __float2half_rn(v1);
    long o = ((long)(z * K + gk) << 12) + n;
    *(__half2*)&oh[o] = __halves2half2(h0, h1);
    *(__half2*)&om[o] = __halves2half2(__float2half_rn(v0 - __half2float(h0)),
                                       __float2half_rn(v1 - __half2float(h1)));
}

// ---------------- conv via mma.sync fp16 3-product: A=[co][k] h/m, B=[k][n] h/m ----------------
// Tile: MROWS co x 128 n, K chunks of 32, 3 stages cp.async.
template <int MROWS>
__global__ void __launch_bounds__(256, 2)
conv_mma_kernel(const __half* __restrict__ Wh, const __half* __restrict__ Wm,
                const __half* __restrict__ Bh, const __half* __restrict__ Bm, int K,
                const float* __restrict__ bias,
                float* __restrict__ outA, long sA, float* __restrict__ outB, long sB) {
    extern __shared__ __align__(16) char csm[];
    const int AG = MROWS * 4;                 // granules per A segment
    const int STB = (2 * AG + 1024) * 16;     // stage bytes
    const int ABYT = 2 * AG * 16;             // A bytes per stage
    const int TMT = MROWS / 32;
    uint32_t sb = smem_u32(csm);
    int z = blockIdx.z, sel = z >> 2, bb = z & 3;
    float* out = sel ? outB : outA;
    long os = sel ? sB : sA;
    int m0 = blockIdx.y * MROWS;
    int n0 = blockIdx.x * 128;
    int tid = threadIdx.x;
    int lane = tid & 31, wid = tid >> 5;
    int wm = wid & 1, wn = wid >> 1;
    long zK = (long)z * K;

    float acc[TMT][4][4];
#pragma unroll
    for (int mt = 0; mt < TMT; mt++)
#pragma unroll
        for (int nt = 0; nt < 4; nt++)
#pragma unroll
            for (int q = 0; q < 4; q++) acc[mt][nt][q] = 0.f;

    auto issue = [&](int c, int st) {
        int kb = c * 32;
        uint32_t da = sb + (uint32_t)st * STB;
        uint32_t db = da + ABYT;
#pragma unroll
        for (int it = 0; it < 2 * AG / 256; it++) {
            int e = tid + it * 256;
            int seg = e / AG;
            int r = (e % AG) >> 2;
            int k8 = e & 3;
            uint32_t g = (uint32_t)(seg * AG + r * 4 + (k8 ^ ((r >> 1) & 3))) << 4;
            const __half* src = (seg ? Wm : Wh) + (long)(m0 + r) * K + kb + k8 * 8;
            CP_ASYNC16(da + g, src);
        }
#pragma unroll
        for (int it = 0; it < 4; it++) {
            int e = tid + it * 256;
            int seg = e >> 9;
            int k = (e >> 4) & 31;
            int ng = e & 15;
            uint32_t g = (uint32_t)(seg * 512 + k * 16 + (ng ^ (k & 15))) << 4;
            const __half* src = (seg ? Bm : Bh) + ((zK + kb + k) << 12) + n0 + ng * 8;
            CP_ASYNC16(db + g, src);
        }
        CP_COMMIT();
    };

    int NCH = K / 32;
    issue(0, 0);
    issue(1, 1);

    for (int c = 0; c < NCH; c++) {
        int st = c % 3;
        if (c + 1 < NCH) CP_WAIT1(); else CP_WAIT0();
        __syncthreads();
        if (c + 2 < NCH) issue(c + 2, (c + 2) % 3);
        uint32_t Ab = sb + (uint32_t)st * STB;
        uint32_t Bb = Ab + ABYT;
#pragma unroll
        for (int ks = 0; ks < 2; ks++) {
            uint32_t bf[2][4][2];
#pragma unroll
            for (int sk = 0; sk < 2; sk++)
#pragma unroll
                for (int nt = 0; nt < 4; nt++) {
                    int k = ks * 16 + (lane & 15);
                    int ng = wn * 4 + nt;
                    uint32_t g = (uint32_t)(sk * 512 + k * 16 + (ng ^ (k & 15))) << 4;
                    LDSM_X2T(bf[sk][nt][0], bf[sk][nt][1], Bb + g);
                }
#pragma unroll
            for (int sq = 0; sq < 2; sq++) {
                uint32_t af[TMT][4];
#pragma unroll
                for (int mt = 0; mt < TMT; mt++) {
                    int row = wm * (MROWS / 2) + mt * 16 + (lane & 15);
                    int k8 = ks * 2 + (lane >> 4);
                    uint32_t g = (uint32_t)(sq * AG + row * 4 + (k8 ^ ((row >> 1) & 3))) << 4;
                    LDSM_X4(af[mt][0], af[mt][1], af[mt][2], af[mt][3], Ab + g);
                }
                int nsk = 2 - sq;  // sq=0: hh,hm ; sq=1: mh
#pragma unroll
                for (int sk = 0; sk < 2; sk++) {
                    if (sk >= nsk) break;
#pragma unroll
                    for (int mt = 0; mt < TMT; mt++)
#pragma unroll
                        for (int nt = 0; nt < 4; nt++) MMA_F16(acc[mt][nt], af[mt], bf[sk][nt]);
                }
            }
        }
    }
    // epilogue: + bias, store fp32
#pragma unroll
    for (int mt = 0; mt < TMT; mt++) {
        int co0 = m0 + wm * (MROWS / 2) + mt * 16 + (lane >> 2);
        int co1 = co0 + 8;
        float b0 = bias[co0], b1 = bias[co1];
        long base0 = (long)bb * os + ((long)co0 << 12) + n0;
        long base1 = (long)bb * os + ((long)co1 << 12) + n0;
#pragma unroll
        for (int nt = 0; nt < 4; nt++) {
            int nn = wn * 32 + nt * 8 + (lane & 3) * 2;
            float2 o0, o1;
            o0.x = acc[mt][nt][0] + b0;
            o0.y = acc[mt][nt][1] + b0;
            o1.x = acc[mt][nt][2] + b1;
            o1.y = acc[mt][nt][3] + b1;
            *(float2*)&out[base0 + nn] = o0;
            *(float2*)&out[base1 + nn] = o1;
        }
    }
}

// ---------------- split to fp16 h/m stacks (512 k each) + key norms ----------------
__global__ void split_kernel(const float* __restrict__ f1out, const float* __restrict__ f2,
                             __half* __restrict__ QS, __half* __restrict__ KS,
                             float* __restrict__ b2n) {
    __shared__ __half sh[2][64][64];
    __shared__ float snorm[256];
    int n0 = blockIdx.x * 64;
    int src = blockIdx.y;
    int b = blockIdx.z;
    const float* f = src ? (f2 + (long)b * C3 * NPIX) : (f1out + (long)b * 512 * NPIX);
    __half* dst = (src ? KS : QS) + (long)b * NPIX * 512;
    int tid = threadIdx.x;
    int nl = tid & 63, cq = tid >> 6;
    float nacc = 0.f;
    for (int cc = 0; cc < 4; cc++) {
        int cbase = cc * 64;
#pragma unroll
        for (int r = 0; r < 16; r++) {
            int cl = cq + r * 4;
            float x = f[(long)(cbase + cl) * NPIX + n0 + nl];
            __half h = __float2half_rn(x);
            sh[0][cl][nl] = h;
            sh[1][cl][nl] = __float2half_rn(x - __half2float(h));
            nacc += x * x;
        }
        __syncthreads();
        int nl2 = tid >> 2;
        int cg = (tid & 3) * 16;
#pragma unroll
        for (int s = 0; s < 2; s++) {
            __half* drow = dst + (long)(n0 + nl2) * 512 + s * 256 + cbase + cg;
#pragma unroll
            for (int j = 0; j < 16; j++) drow[j] = sh[s][cg + j][nl2];
        }
        __syncthreads();
    }
    if (src == 1) {
        snorm[tid] = nacc;
        __syncthreads();
        if (tid < 64)
            b2n[(long)b * NPIX + n0 + tid] =
                snorm[tid] + snorm[tid + 64] + snorm[tid + 128] + snorm[tid + 192];
    }
}

// ---------------- dist GEMM + argmin: fp16 2-segment, 3 products (round-14 proven) ----------------
#define MST 32768
#define MSM_TOTAL (3 * MST)

__global__ void __launch_bounds__(256, 2)
dist_mma_kernel(const __half* __restrict__ QS, const __half* __restrict__ KS,
                const float* __restrict__ b2n, float* __restrict__ pval,
                int* __restrict__ pidx) {
    extern __shared__ __align__(16) char dsm[];
    uint32_t sb = smem_u32(dsm);
    int b = blockIdx.z;
    int jq = blockIdx.y;
    int j0 = jq * 128;
    int i0 = blockIdx.x * 128;
    int tid = threadIdx.x;
    int lane = tid & 31, wid = tid >> 5;
    int wm = wid & 1, wn = wid >> 1;

    const __half* Qb = QS + (long)(b * NPIX + i0) * 512;
    const __half* Kb = KS + (long)(b * NPIX + j0) * 512;
    const float* bn = b2n + (long)b * NPIX;

    float acc[4][4][4];
#pragma unroll
    for (int mt = 0; mt < 4; mt++)
#pragma unroll
        for (int nt = 0; nt < 4; nt++)
#pragma unroll
            for (int q = 0; q < 4; q++) acc[mt][nt][q] = 0.f;

    auto issue = [&](int c, int st) {
        uint32_t dq = sb + (uint32_t)st * MST;
        uint32_t dk = dq + 16384;
        int kb = c * 32;
#pragma unroll
        for (int it = 0; it < 4; it++) {
            int e = tid + it * 256;
            int s = e >> 9;
            int row = (e >> 2) & 127;
            int k8 = e & 3;
            uint32_t g = (uint32_t)((s << 9) + row * 4 + (k8 ^ ((row >> 1) & 3))) << 4;
            const __half* sq = Qb + (long)row * 512 + s * 256 + kb + k8 * 8;
            const __half* sk = Kb + (long)row * 512 + s * 256 + kb + k8 * 8;
            CP_ASYNC16(dq + g, sq);
            CP_ASYNC16(dk + g, sk);
        }
        CP_COMMIT();
    };

    const int NCH = 8;
    issue(0, 0);
    issue(1, 1);

    for (int c = 0; c < NCH; c++) {
        int st = c % 3;
        if (c + 1 < NCH) CP_WAIT1(); else CP_WAIT0();
        __syncthreads();
        if (c + 2 < NCH) issue(c + 2, (c + 2) % 3);
        uint32_t Ab = sb + (uint32_t)st * MST;
        uint32_t Bb = Ab + 16384;
#pragma unroll
        for (int ks = 0; ks < 2; ks++) {
            uint32_t bf[2][4][2];
#pragma unroll
            for (int sk = 0; sk < 2; sk++)
#pragma unroll
                for (int nt = 0; nt < 4; nt++) {
                    int rowb = wn * 32 + nt * 8 + (lane & 7);
                    int k8 = ks * 2 + ((lane >> 3) & 1);
                    uint32_t g = (uint32_t)((sk << 9) + rowb * 4 + (k8 ^ ((rowb >> 1) & 3))) << 4;
                    LDSM_X2(bf[sk][nt][0], bf[sk][nt][1], Bb + g);
                }
#pragma unroll
            for (int sq = 0; sq < 2; sq++) {
                uint32_t af[4][4];
#pragma unroll
                for (int mt = 0; mt < 4; mt++) {
                    int row = wm * 64 + mt * 16 + (lane & 15);
                    int k8 = ks * 2 + (lane >> 4);
                    uint32_t g = (uint32_t)((sq << 9) + row * 4 + (k8 ^ ((row >> 1) & 3))) << 4;
                    LDSM_X4(af[mt][0], af[mt][1], af[mt][2], af[mt][3], Ab + g);
                }
                int nsk = 2 - sq;
#pragma unroll
                for (int sk = 0; sk < 2; sk++) {
                    if (sk >= nsk) break;
#pragma unroll
                    for (int mt = 0; mt < 4; mt++)
#pragma unroll
                        for (int nt = 0; nt < 4; nt++) MMA_F16(acc[mt][nt], af[mt], bf[sk][nt]);
                }
            }
        }
    }

    float bnv[4][2];
#pragma unroll
    for (int nt = 0; nt < 4; nt++) {
        int jj = j0 + wn * 32 + nt * 8 + (lane & 3) * 2;
        bnv[nt][0] = __ldg(&bn[jj]);
        bnv[nt][1] = __ldg(&bn[jj + 1]);
    }
    float bvA[4], bvB[4];
    int biA[4], biB[4];
#pragma unroll
    for (int mt = 0; mt < 4; mt++) {
        bvA[mt] = 3.4e38f; biA[mt] = 0;
        bvB[mt] = 3.4e38f; biB[mt] = 0;
#pragma unroll
        for (int nt = 0; nt < 4; nt++)
#pragma unroll
            for (int p = 0; p < 2; p++) {
                int j = j0 + wn * 32 + nt * 8 + (lane & 3) * 2 + p;
                float dA = bnv[nt][p] - 2.f * acc[mt][nt][p];
                if (dA < bvA[mt]) { bvA[mt] = dA; biA[mt] = j; }
                float dB = bnv[nt][p] - 2.f * acc[mt][nt][2 + p];
                if (dB < bvB[mt]) { bvB[mt] = dB; biB[mt] = j; }
            }
#pragma unroll
        for (int m = 1; m <= 2; m <<= 1) {
            float ov = __shfl_xor_sync(0xffffffffu, bvA[mt], m);
            int oi = __shfl_xor_sync(0xffffffffu, biA[mt], m);
            if (ov < bvA[mt] || (ov == bvA[mt] && oi < biA[mt])) { bvA[mt] = ov; biA[mt] = oi; }
            ov = __shfl_xor_sync(0xffffffffu, bvB[mt], m);
            oi = __shfl_xor_sync(0xffffffffu, biB[mt], m);
            if (ov < bvB[mt] || (ov == bvB[mt] && oi < biB[mt])) { bvB[mt] = ov; biB[mt] = oi; }
        }
    }
    __syncthreads();
    float* rv = (float*)dsm;
    int* ri = (int*)(dsm + 2048);
    if ((lane & 3) == 0) {
#pragma unroll
        for (int mt = 0; mt < 4; mt++) {
            int r = wm * 64 + mt * 16 + (lane >> 2);
            rv[wn * 128 + r] = bvA[mt];
            ri[wn * 128 + r] = biA[mt];
            rv[wn * 128 + r + 8] = bvB[mt];
            ri[wn * 128 + r + 8] = biB[mt];
        }
    }
    __syncthreads();
    if (tid < 128) {
        float bv = rv[tid];
        int bi = ri[tid];
#pragma unroll
        for (int w = 1; w < 4; w++) {
            float v = rv[w * 128 + tid];
            int ii = ri[w * 128 + tid];
            if (v < bv || (v == bv && ii < bi)) { bv = v; bi = ii; }
        }
        long o = ((long)(jq * NB + b) << 12) + i0 + tid;
        pval[o] = bv;
        pidx[o] = bi;
    }
}

// ---------------- merge 32 j-tile candidates ----------------
__global__ void merge_kernel(const float* __restrict__ pval, const int* __restrict__ pidx,
                             int* __restrict__ idxout) {
    int t = blockIdx.x * blockDim.x + threadIdx.x;
    if (t >= NB * NPIX) return;
    int b = t >> 12, i = t & (NPIX - 1);
    float bv = 3.4e38f;
    int bi = 0;
#pragma unroll 4
    for (int jq = 0; jq < 32; jq++) {
        long o = ((long)(jq * NB + b) << 12) + i;
        float v = pval[o];
        int ii = pidx[o];
        if (v < bv || (v == bv && ii < bi)) { bv = v; bi = ii; }
    }
    idxout[t] = bi;
}

// ---------------- gather ----------------
__global__ void gather_kernel(const float* __restrict__ f2, const int* __restrict__ idx,
                              float* __restrict__ out) {
    long t = (long)blockIdx.x * blockDim.x + threadIdx.x;
    if (t >= (long)NB * C3 * NPIX) return;
    int j = (int)(t & (NPIX - 1));
    int c = (int)((t >> 12) & 255);
    int b = (int)(t >> 20);
    int id = idx[(long)b * NPIX + j];
    out[((long)b * 512 + 256 + c) * NPIX + j] = f2[((long)b * C3 + c) * NPIX + id];
}

// ---------------- launch ----------------
extern "C" void kernel_launch(void* const* d_in, const int* in_sizes, int n_in,
                              void* d_out, int out_size) {
    const float* x1 = (const float*)d_in[0];
    const float* x2 = (const float*)d_in[1];
    const float* w1 = (const float*)d_in[2];
    const float* b1 = (const float*)d_in[3];
    const float* w2 = (const float*)d_in[4];
    const float* b2 = (const float*)d_in[5];
    const float* w3 = (const float*)d_in[6];
    const float* b3 = (const float*)d_in[7];
    float* out = (float*)d_out;

    float *T1, *T2, *F2, *B2N, *PVAL;
    int *IDX, *PIDX;
    __half *ICh, *ICm, *Wh2, *Wm2, *Wh3, *Wm3, *QS, *KS;
    cudaGetSymbolAddress((void**)&T1, g_T1);
    cudaGetSymbolAddress((void**)&T2, g_T2);
    cudaGetSymbolAddress((void**)&ICh, g_ICh);
    cudaGetSymbolAddress((void**)&ICm, g_ICm);
    cudaGetSymbolAddress((void**)&F2, g_F2);
    cudaGetSymbolAddress((void**)&B2N, g_B2N);
    cudaGetSymbolAddress((void**)&IDX, g_IDX);
    cudaGetSymbolAddress((void**)&Wh2, g_Wh2);
    cudaGetSymbolAddress((void**)&Wm2, g_Wm2);
    cudaGetSymbolAddress((void**)&Wh3, g_Wh3);
    cudaGetSymbolAddress((void**)&Wm3, g_Wm3);
    cudaGetSymbolAddress((void**)&PVAL, g_PVAL);
    cudaGetSymbolAddress((void**)&PIDX, g_PIDX);
    cudaGetSymbolAddress((void**)&QS, g_QS);
    cudaGetSymbolAddress((void**)&KS, g_KS);

    cudaFuncSetAttribute(dist_mma_kernel, cudaFuncAttributeMaxDynamicSharedMemorySize,
                         MSM_TOTAL);
    // conv3: stage (2*512 + 1024)*16 = 32768 ; conv2: (2*256 + 1024)*16 = 24576
    cudaFuncSetAttribute(conv_mma_kernel<128>, cudaFuncAttributeMaxDynamicSharedMemorySize,
                         3 * 32768);
    cudaFuncSetAttribute(conv_mma_kernel<64>, cudaFuncAttributeMaxDynamicSharedMemorySize,
                         3 * 24576);

    prep_kernel<<<(C2 * 288 + C3 * 576 + 255) / 256, 256>>>(w2, w3, Wh2, Wm2, Wh3, Wm3);
    conv1_kernel<<<dim3(NPIX / 256, 8), 256>>>(x1, x2, w1, b1, T1);
    im2col_kernel<<<dim3(288, 8, 8), 256>>>(T1, C1, ICh, ICm);
    conv_mma_kernel<64><<<dim3(32, 1, 8), 256, 3 * 24576>>>(
        Wh2, Wm2, ICh, ICm, 288, b2, T2, (long)C2 * NPIX, T2 + (long)NB * C2 * NPIX,
        (long)C2 * NPIX);
    im2col_kernel<<<dim3(576, 8, 8), 256>>>(T2, C2, ICh, ICm);
    conv_mma_kernel<128><<<dim3(32, 2, 8), 256, 3 * 32768>>>(
        Wh3, Wm3, ICh, ICm, 576, b3, out, (long)512 * NPIX, F2, (long)C3 * NPIX);
    split_kernel<<<dim3(NPIX / 64, 2, NB), 256>>>(out, F2, QS, KS, B2N);
    dist_mma_kernel<<<dim3(32, 32, NB), 256, MSM_TOTAL>>>(QS, KS, B2N, PVAL, PIDX);
    merge_kernel<<<(NB * NPIX + 255) / 256, 256>>>(PVAL, PIDX, IDX);
    gather_kernel<<<(int)(((long)NB * C3 * NPIX + 255) / 256), 256>>>(F2, IDX, out);
}